// round 8
// baseline (speedup 1.0000x reference)
#include <cuda_runtime.h>
#include <cuda_fp16.h>
#include <cstdint>
#include <cstddef>

// Problem constants
#define BB 2
#define TT 2048
#define CC 2048
#define HH 16
#define DH 128
#define M_ROWS (BB*TT)          // 4096
#define QKV_N  (3*CC)           // 6144

// Scratch (allocation-free rule: __device__ globals)
__device__ __half g_xh  [(size_t)M_ROWS * CC];      // x fp16        16 MB
__device__ __half g_qkvh[(size_t)M_ROWS * QKV_N];   // qkv fp16      48 MB
__device__ __half g_yh  [(size_t)M_ROWS * CC];      // attn out fp16 16 MB
__device__ __half g_wath[(size_t)QKV_N * CC];       // W_attn^T fp16 24 MB
__device__ __half g_wpth[(size_t)CC * CC];          // W_proj^T fp16  8 MB

// ---------------------------------------------------------------------------
// PTX helpers (all plain sm_80+)
// ---------------------------------------------------------------------------
__device__ __forceinline__ void mma_h(float* c, const uint32_t* a, const uint32_t* b) {
    asm volatile(
        "mma.sync.aligned.m16n8k16.row.col.f32.f16.f16.f32 "
        "{%0,%1,%2,%3}, {%4,%5,%6,%7}, {%8,%9}, {%0,%1,%2,%3};"
        : "+f"(c[0]), "+f"(c[1]), "+f"(c[2]), "+f"(c[3])
        : "r"(a[0]), "r"(a[1]), "r"(a[2]), "r"(a[3]), "r"(b[0]), "r"(b[1]));
}

__device__ __forceinline__ uint32_t pack_h2(float lo, float hi) {
    __half2 h = __floats2half2_rn(lo, hi);
    return *(uint32_t*)&h;
}

__device__ __forceinline__ uint32_t smem_u32(const void* p) {
    uint32_t a;
    asm("{ .reg .u64 t; cvta.to.shared.u64 t, %1; cvt.u32.u64 %0, t; }"
        : "=r"(a) : "l"(p));
    return a;
}

__device__ __forceinline__ void ldsm_x4(uint32_t* r, uint32_t addr) {
    asm volatile("ldmatrix.sync.aligned.m8n8.x4.shared.b16 {%0,%1,%2,%3}, [%4];"
                 : "=r"(r[0]), "=r"(r[1]), "=r"(r[2]), "=r"(r[3]) : "r"(addr));
}

__device__ __forceinline__ void cp16(uint32_t saddr, const void* gaddr) {
    asm volatile("cp.async.cg.shared.global [%0], [%1], 16;"
                 :: "r"(saddr), "l"(gaddr));
}
#define CP_COMMIT() asm volatile("cp.async.commit_group;" ::: "memory")
#define CP_WAIT1()  asm volatile("cp.async.wait_group 1;" ::: "memory")
#define CP_WAIT0()  asm volatile("cp.async.wait_group 0;" ::: "memory")

// ---------------------------------------------------------------------------
// Pre-pass: f32 -> f16 convert
// ---------------------------------------------------------------------------
__global__ __launch_bounds__(256)
void f2h_kernel(const float* __restrict__ in, __half* __restrict__ out) {
    size_t i = (size_t)blockIdx.x * 256 + threadIdx.x;
    float4 v = ((const float4*)in)[i];
    uint2 o;
    o.x = pack_h2(v.x, v.y);
    o.y = pack_h2(v.z, v.w);
    ((uint2*)out)[i] = o;
}

// ---------------------------------------------------------------------------
// Pre-pass: transpose + convert: in [R][Cn] f32 -> out [Cn][R] f16
// ---------------------------------------------------------------------------
__global__ void trans_h_kernel(const float* __restrict__ in, __half* __restrict__ out,
                               int R, int Cn) {
    __shared__ float t[32][33];
    int bx = blockIdx.x * 32, by = blockIdx.y * 32;
    int tx = threadIdx.x, ty = threadIdx.y;   // (32, 8)
#pragma unroll
    for (int j = 0; j < 32; j += 8)
        t[ty + j][tx] = in[(size_t)(by + ty + j) * Cn + bx + tx];
    __syncthreads();
#pragma unroll
    for (int j = 0; j < 32; j += 8)
        out[(size_t)(bx + ty + j) * R + by + tx] = __float2half_rn(t[tx][ty + j]);
}

// ---------------------------------------------------------------------------
// fp16 GEMM:  C[M,N] = A[M,K]h @ Bt[N,K]h^T + bias[N]
// BM=128, BN=256, BK=32 halfs. 512 threads = 16 warps (4m x 4n),
// warp tile 32x64. cp.async 3-stage pipeline + ldmatrix fragments.
// smem rows: 16 u32 data + 4 pad (GROW=20), conflict-free for ldmatrix.
// ---------------------------------------------------------------------------
#define GBM 128
#define GBN 256
#define GBK 32
#define GROW 20
#define A_TILE_U32 (128 * GROW)          // 2560
#define B_TILE_U32 (256 * GROW)          // 5120
#define STAGES 3
#define GEMM_SMEM ((A_TILE_U32 + B_TILE_U32) * STAGES * 4)   // 92160 B

__global__ __launch_bounds__(512, 1)
void h_gemm_kernel(const __half* __restrict__ A, const __half* __restrict__ Bt,
                   const float* __restrict__ bias,
                   float* __restrict__ Cf, __half* __restrict__ Ch,
                   float* __restrict__ cache,
                   int M, int N, int K) {
    extern __shared__ uint32_t smu[];
    const uint32_t sbase = smem_u32(smu);
    const uint32_t sA = sbase;                                // [STAGES][A_TILE]
    const uint32_t sB = sbase + STAGES * A_TILE_U32 * 4;      // [STAGES][B_TILE]

    const int tid  = threadIdx.x;
    const int wid  = tid >> 5;
    const int lane = tid & 31;
    const int g    = lane >> 2;
    const int tg   = lane & 3;
    const int wm   = (wid & 3) * 32;
    const int wn   = (wid >> 2) * 64;
    const int m0   = blockIdx.y * GBM;
    const int n0   = blockIdx.x * GBN;
    const int rowu4 = K / 8;

    // cp.async coords: A 1x16B, B 2x16B per thread per stage
    const uint4* gA0; uint32_t soA;
    {
        int r = tid >> 2, c4 = tid & 3;
        gA0 = (const uint4*)A + (size_t)(m0 + r) * rowu4 + c4;
        soA = (uint32_t)(r * GROW + c4 * 4) * 4;
    }
    const uint4* gB[2]; uint32_t soB[2];
#pragma unroll
    for (int i = 0; i < 2; i++) {
        int idx = i * 512 + tid;
        int r = idx >> 2, c4 = idx & 3;
        gB[i] = (const uint4*)Bt + (size_t)(n0 + r) * rowu4 + c4;
        soB[i] = (uint32_t)(r * GROW + c4 * 4) * 4;
    }

    // ldmatrix lane addressing (identical math to R7 - verified)
    const int mrow = lane & 7;
    const int msel = lane >> 3;
    uint32_t aOff[2];
#pragma unroll
    for (int i = 0; i < 2; i++)
        aOff[i] = (uint32_t)(((wm + 16 * i + (msel & 1) * 8 + mrow) * GROW
                             + (msel >> 1) * 4) * 4);
    uint32_t bOff[4];
#pragma unroll
    for (int jj = 0; jj < 4; jj++)
        bOff[jj] = (uint32_t)(((wn + 16 * jj + (msel >> 1) * 8 + mrow) * GROW
                              + (msel & 1) * 4) * 4);

    float c[2][8][4];
#pragma unroll
    for (int i = 0; i < 2; i++)
#pragma unroll
        for (int j = 0; j < 8; j++)
#pragma unroll
            for (int q = 0; q < 4; q++) c[i][j][q] = 0.0f;

    const int NC = K / GBK;

    // Prologue: stages 0, 1
#pragma unroll
    for (int st = 0; st < 2; st++) {
        uint32_t aS = sA + st * A_TILE_U32 * 4;
        uint32_t bS = sB + st * B_TILE_U32 * 4;
        cp16(aS + soA, gA0 + st * 4);
#pragma unroll
        for (int i = 0; i < 2; i++)
            cp16(bS + soB[i], gB[i] + st * 4);
        CP_COMMIT();
    }

    for (int ch = 0; ch < NC; ++ch) {
        if (ch + 1 < NC) { CP_WAIT1(); } else { CP_WAIT0(); }
        __syncthreads();

        if (ch + 2 < NC) {
            int st = (ch + 2) % STAGES;
            uint32_t aS = sA + st * A_TILE_U32 * 4;
            uint32_t bS = sB + st * B_TILE_U32 * 4;
            cp16(aS + soA, gA0 + (ch + 2) * 4);
#pragma unroll
            for (int i = 0; i < 2; i++)
                cp16(bS + soB[i], gB[i] + (ch + 2) * 4);
            CP_COMMIT();
        }

        const int cur = ch % STAGES;
        const uint32_t aS = sA + cur * A_TILE_U32 * 4;
        const uint32_t bS = sB + cur * B_TILE_U32 * 4;

#pragma unroll
        for (int s = 0; s < 2; s++) {
            uint32_t a[2][4], bq[4][4];
#pragma unroll
            for (int i = 0; i < 2; i++)
                ldsm_x4(a[i], aS + aOff[i] + s * 32);
#pragma unroll
            for (int jj = 0; jj < 4; jj++)
                ldsm_x4(bq[jj], bS + bOff[jj] + s * 32);
#pragma unroll
            for (int i = 0; i < 2; i++)
#pragma unroll
                for (int jj = 0; jj < 4; jj++) {
                    mma_h(c[i][2 * jj],     a[i], &bq[jj][0]);
                    mma_h(c[i][2 * jj + 1], a[i], &bq[jj][2]);
                }
        }
    }

    // Epilogue
#pragma unroll
    for (int i = 0; i < 2; i++) {
        int row = m0 + wm + 16 * i + g;
#pragma unroll
        for (int j = 0; j < 8; j++) {
            int col = n0 + wn + 8 * j + 2 * tg;
            float2 bv = *(const float2*)(bias + col);
            float2 o0, o1;
            o0.x = c[i][j][0] + bv.x;  o0.y = c[i][j][1] + bv.y;
            o1.x = c[i][j][2] + bv.x;  o1.y = c[i][j][3] + bv.y;
            if (Cf != nullptr) {
                *(float2*)(Cf + (size_t)row * N + col) = o0;
                *(float2*)(Cf + (size_t)(row + 8) * N + col) = o1;
            }
            if (Ch != nullptr) {
                *(uint32_t*)(Ch + (size_t)row * N + col) = pack_h2(o0.x, o0.y);
                *(uint32_t*)(Ch + (size_t)(row + 8) * N + col) = pack_h2(o1.x, o1.y);
            }
            if (cache != nullptr && col >= CC) {
                int cc = col - CC;
                *(float2*)(cache + (size_t)row * (2 * CC) + cc) = o0;
                *(float2*)(cache + (size_t)(row + 8) * (2 * CC) + cc) = o1;
            }
        }
    }
}

// ---------------------------------------------------------------------------
// Flash attention, fp16 mma (causal). Grid: (B*H, T/128). 256 threads.
// smem (u32): Qs[128][68], Ks[64][68], Vt[128][36], Ps[128][36]
// ---------------------------------------------------------------------------
#define AQW 68
#define AVW 36
#define ATTN_SMEM_U32 (128*AQW + 64*AQW + 128*AVW + 128*AVW)
#define ATTN_SMEM_BYTES (ATTN_SMEM_U32 * 4)

__global__ __launch_bounds__(256)
void attn_h_kernel(const __half* __restrict__ qkv, __half* __restrict__ y) {
    extern __shared__ uint32_t smu[];
    uint32_t* Qs = smu;                   // [128][68]
    uint32_t* Ks = Qs + 128 * AQW;        // [64][68]
    uint32_t* Vt = Ks + 64 * AQW;         // [128][36]
    uint32_t* Ps = Vt + 128 * AVW;        // [128][36]

    const int tid  = threadIdx.x;
    const int wid  = tid >> 5;
    const int lane = tid & 31;
    const int g    = lane >> 2;
    const int tg   = lane & 3;
    const int bh   = blockIdx.x;
    const int b    = bh >> 4;
    const int h    = bh & 15;
    const int qt   = gridDim.y - 1 - blockIdx.y;
    const int q0   = qt * 128;
    const int wr0  = wid * 16;

    const float SCALE = 0.08838834764831845f;
    const int ROWU4 = QKV_N / 8;          // 768

    const uint4* qkv4 = (const uint4*)qkv;
    const size_t bbase = (size_t)b * TT * ROWU4;
    const int qoff = h * 16;
    const int koff = 256 + h * 16;
    const int voff = 512 + h * 16;

#pragma unroll
    for (int p = 0; p < 8; p++) {
        int i = tid + 256 * p;
        int r = i >> 4, c4 = i & 15;
        uint4 v = qkv4[bbase + (size_t)(q0 + r) * ROWU4 + qoff + c4];
        *(uint4*)&Qs[r * AQW + c4 * 4] = v;
    }

    float m_prev[2] = {-1e30f, -1e30f};
    float l_acc[2]  = {0.0f, 0.0f};
    float acc[16][4];
#pragma unroll
    for (int nj = 0; nj < 16; nj++)
#pragma unroll
        for (int q = 0; q < 4; q++) acc[nj][q] = 0.0f;

    const int ntiles = 2 * qt + 2;

    for (int kt = 0; kt < ntiles; ++kt) {
        const int k0 = kt * 64;
        __syncthreads();

#pragma unroll
        for (int p = 0; p < 4; p++) {
            int i = tid + 256 * p;
            int r = i >> 4, c4 = i & 15;
            uint4 v = qkv4[bbase + (size_t)(k0 + r) * ROWU4 + koff + c4];
            *(uint4*)&Ks[r * AQW + c4 * 4] = v;
        }
#pragma unroll
        for (int p = 0; p < 2; p++) {
            int t = tid + 256 * p;
            int pr = t & 31;
            int dc = t >> 5;
            union { uint4 v; unsigned short s[8]; } ua, ub;
            ua.v = qkv4[bbase + (size_t)(k0 + 2 * pr)     * ROWU4 + voff + dc];
            ub.v = qkv4[bbase + (size_t)(k0 + 2 * pr + 1) * ROWU4 + voff + dc];
#pragma unroll
            for (int j = 0; j < 8; j++)
                Vt[(dc * 8 + j) * AVW + pr] =
                    (uint32_t)ua.s[j] | ((uint32_t)ub.s[j] << 16);
        }
        __syncthreads();

        float cs[8][4];
#pragma unroll
        for (int j = 0; j < 8; j++)
#pragma unroll
            for (int q = 0; q < 4; q++) cs[j][q] = 0.0f;

#pragma unroll
        for (int s = 0; s < 8; s++) {
            uint32_t a[4];
            a[0] = Qs[(wr0 + g)     * AQW + s * 8 + tg];
            a[1] = Qs[(wr0 + g + 8) * AQW + s * 8 + tg];
            a[2] = Qs[(wr0 + g)     * AQW + s * 8 + tg + 4];
            a[3] = Qs[(wr0 + g + 8) * AQW + s * 8 + tg + 4];
#pragma unroll
            for (int j = 0; j < 8; j++) {
                uint32_t bf[2];
                bf[0] = Ks[(8 * j + g) * AQW + s * 8 + tg];
                bf[1] = Ks[(8 * j + g) * AQW + s * 8 + tg + 4];
                mma_h(cs[j], a, bf);
            }
        }

        const int gr0 = q0 + wr0 + g;
        const int gr1 = gr0 + 8;
        float mx0 = -1e30f, mx1 = -1e30f;
#pragma unroll
        for (int j = 0; j < 8; j++) {
            int gc0 = k0 + 8 * j + 2 * tg;
            int gc1 = gc0 + 1;
            float s0 = cs[j][0] * SCALE; if (gc0 > gr0) s0 = -1e30f;
            float s1 = cs[j][1] * SCALE; if (gc1 > gr0) s1 = -1e30f;
            float s2 = cs[j][2] * SCALE; if (gc0 > gr1) s2 = -1e30f;
            float s3 = cs[j][3] * SCALE; if (gc1 > gr1) s3 = -1e30f;
            cs[j][0] = s0; cs[j][1] = s1; cs[j][2] = s2; cs[j][3] = s3;
            mx0 = fmaxf(mx0, fmaxf(s0, s1));
            mx1 = fmaxf(mx1, fmaxf(s2, s3));
        }
        mx0 = fmaxf(mx0, __shfl_xor_sync(0xffffffffu, mx0, 1));
        mx0 = fmaxf(mx0, __shfl_xor_sync(0xffffffffu, mx0, 2));
        mx1 = fmaxf(mx1, __shfl_xor_sync(0xffffffffu, mx1, 1));
        mx1 = fmaxf(mx1, __shfl_xor_sync(0xffffffffu, mx1, 2));

        float mn0 = fmaxf(m_prev[0], mx0);
        float mn1 = fmaxf(m_prev[1], mx1);
        float f0 = __expf(m_prev[0] - mn0);
        float f1 = __expf(m_prev[1] - mn1);
        m_prev[0] = mn0; m_prev[1] = mn1;

        float ls0 = 0.0f, ls1 = 0.0f;
#pragma unroll
        for (int j = 0; j < 8; j++) {
            float p0 = __expf(cs[j][0] - mn0);
            float p1 = __expf(cs[j][1] - mn0);
            float p2 = __expf(cs[j][2] - mn1);
            float p3 = __expf(cs[j][3] - mn1);
            ls0 += p0 + p1;
            ls1 += p2 + p3;
            Ps[(wr0 + g)     * AVW + 4 * j + tg] = pack_h2(p0, p1);
            Ps[(wr0 + g + 8) * AVW + 4 * j + tg] = pack_h2(p2, p3);
        }
        ls0 += __shfl_xor_sync(0xffffffffu, ls0, 1);
        ls0 += __shfl_xor_sync(0xffffffffu, ls0, 2);
        ls1 += __shfl_xor_sync(0xffffffffu, ls1, 1);
        ls1 += __shfl_xor_sync(0xffffffffu, ls1, 2);
        l_acc[0] = l_acc[0] * f0 + ls0;
        l_acc[1] = l_acc[1] * f1 + ls1;

#pragma unroll
        for (int nj = 0; nj < 16; nj++) {
            acc[nj][0] *= f0; acc[nj][1] *= f0;
            acc[nj][2] *= f1; acc[nj][3] *= f1;
        }
        __syncwarp();

#pragma unroll
        for (int s = 0; s < 4; s++) {
            uint32_t a[4];
            a[0] = Ps[(wr0 + g)     * AVW + s * 8 + tg];
            a[1] = Ps[(wr0 + g + 8) * AVW + s * 8 + tg];
            a[2] = Ps[(wr0 + g)     * AVW + s * 8 + tg + 4];
            a[3] = Ps[(wr0 + g + 8) * AVW + s * 8 + tg + 4];
#pragma unroll
            for (int nj = 0; nj < 16; nj++) {
                uint32_t bf[2];
                bf[0] = Vt[(8 * nj + g) * AVW + s * 8 + tg];
                bf[1] = Vt[(8 * nj + g) * AVW + s * 8 + tg + 4];
                mma_h(acc[nj], a, bf);
            }
        }
        __syncwarp();
    }

    float inv0 = 1.0f / l_acc[0];
    float inv1 = 1.0f / l_acc[1];
    size_t row0 = (size_t)(b * TT + q0 + wr0 + g);
    size_t row1 = row0 + 8;
#pragma unroll
    for (int nj = 0; nj < 16; nj++) {
        int col = h * DH + 8 * nj + 2 * tg;
        *(uint32_t*)(y + row0 * CC + col) = pack_h2(acc[nj][0] * inv0, acc[nj][1] * inv0);
        *(uint32_t*)(y + row1 * CC + col) = pack_h2(acc[nj][2] * inv1, acc[nj][3] * inv1);
    }
}

// ---------------------------------------------------------------------------
extern "C" void kernel_launch(void* const* d_in, const int* in_sizes, int n_in,
                              void* d_out, int out_size) {
    (void)in_sizes; (void)n_in; (void)out_size;
    const float* x      = (const float*)d_in[0];
    const float* W_attn = (const float*)d_in[2];
    const float* b_attn = (const float*)d_in[3];
    const float* W_proj = (const float*)d_in[4];
    const float* b_proj = (const float*)d_in[5];

    float* out   = (float*)d_out;
    float* y_out = out;
    float* cache = out + (size_t)M_ROWS * CC;

    __half *xh, *qkvh, *yh, *wath, *wpth;
    cudaGetSymbolAddress((void**)&xh,   g_xh);
    cudaGetSymbolAddress((void**)&qkvh, g_qkvh);
    cudaGetSymbolAddress((void**)&yh,   g_yh);
    cudaGetSymbolAddress((void**)&wath, g_wath);
    cudaGetSymbolAddress((void**)&wpth, g_wpth);

    cudaFuncSetAttribute(h_gemm_kernel,
                         cudaFuncAttributeMaxDynamicSharedMemorySize, GEMM_SMEM);
    cudaFuncSetAttribute(attn_h_kernel,
                         cudaFuncAttributeMaxDynamicSharedMemorySize, ATTN_SMEM_BYTES);

    // 0) pre-pass conversions
    f2h_kernel<<<(int)((size_t)M_ROWS * CC / 4 / 256), 256>>>(x, xh);
    {
        dim3 blk(32, 8);
        trans_h_kernel<<<dim3(QKV_N / 32, CC / 32), blk>>>(W_attn, wath, CC, QKV_N);
        trans_h_kernel<<<dim3(CC / 32, CC / 32), blk>>>(W_proj, wpth, CC, CC);
    }
    // 1) qkv = x @ W_attn + b_attn -> qkv fp16 + fused f32 cache
    {
        dim3 grid(QKV_N / GBN, M_ROWS / GBM);   // (24, 32)
        h_gemm_kernel<<<grid, 512, GEMM_SMEM>>>(xh, wath, b_attn,
                                                nullptr, qkvh, cache,
                                                M_ROWS, QKV_N, CC);
    }
    // 2) flash attention fp16 -> yh
    {
        dim3 grid(BB * HH, TT / 128);           // (32, 16)
        attn_h_kernel<<<grid, 256, ATTN_SMEM_BYTES>>>(qkvh, yh);
    }
    // 3) y = yh @ W_proj + b_proj -> f32 out
    {
        dim3 grid(CC / GBN, M_ROWS / GBM);      // (8, 32)
        h_gemm_kernel<<<grid, 512, GEMM_SMEM>>>(yh, wpth, b_proj,
                                                y_out, nullptr, nullptr,
                                                M_ROWS, CC, CC);
    }
}

// round 9
// speedup vs baseline: 1.1084x; 1.1084x over previous
#include <cuda_runtime.h>
#include <cuda_fp16.h>
#include <cstdint>
#include <cstddef>

// Problem constants
#define BB 2
#define TT 2048
#define CC 2048
#define HH 16
#define DH 128
#define M_ROWS (BB*TT)          // 4096
#define QKV_N  (3*CC)           // 6144

// Scratch (allocation-free rule: __device__ globals)
__device__ __half g_xh  [(size_t)M_ROWS * CC];      // x fp16        16 MB
__device__ __half g_qkvh[(size_t)M_ROWS * QKV_N];   // qkv fp16      48 MB
__device__ __half g_yh  [(size_t)M_ROWS * CC];      // attn out fp16 16 MB
__device__ __half g_wath[(size_t)QKV_N * CC];       // W_attn^T fp16 24 MB
__device__ __half g_wpth[(size_t)CC * CC];          // W_proj^T fp16  8 MB

// ---------------------------------------------------------------------------
// PTX helpers (all plain sm_80+)
// ---------------------------------------------------------------------------
__device__ __forceinline__ void mma_h(float* c, const uint32_t* a, const uint32_t* b) {
    asm volatile(
        "mma.sync.aligned.m16n8k16.row.col.f32.f16.f16.f32 "
        "{%0,%1,%2,%3}, {%4,%5,%6,%7}, {%8,%9}, {%0,%1,%2,%3};"
        : "+f"(c[0]), "+f"(c[1]), "+f"(c[2]), "+f"(c[3])
        : "r"(a[0]), "r"(a[1]), "r"(a[2]), "r"(a[3]), "r"(b[0]), "r"(b[1]));
}

__device__ __forceinline__ uint32_t pack_h2(float lo, float hi) {
    __half2 h = __floats2half2_rn(lo, hi);
    return *(uint32_t*)&h;
}

__device__ __forceinline__ uint32_t smem_u32(const void* p) {
    uint32_t a;
    asm("{ .reg .u64 t; cvta.to.shared.u64 t, %1; cvt.u32.u64 %0, t; }"
        : "=r"(a) : "l"(p));
    return a;
}

__device__ __forceinline__ void ldsm_x4(uint32_t* r, uint32_t addr) {
    asm volatile("ldmatrix.sync.aligned.m8n8.x4.shared.b16 {%0,%1,%2,%3}, [%4];"
                 : "=r"(r[0]), "=r"(r[1]), "=r"(r[2]), "=r"(r[3]) : "r"(addr));
}

__device__ __forceinline__ void cp16(uint32_t saddr, const void* gaddr) {
    asm volatile("cp.async.cg.shared.global [%0], [%1], 16;"
                 :: "r"(saddr), "l"(gaddr));
}
#define CP_COMMIT() asm volatile("cp.async.commit_group;" ::: "memory")
#define CP_WAIT2()  asm volatile("cp.async.wait_group 2;" ::: "memory")
#define CP_WAIT1()  asm volatile("cp.async.wait_group 1;" ::: "memory")
#define CP_WAIT0()  asm volatile("cp.async.wait_group 0;" ::: "memory")

// ---------------------------------------------------------------------------
// Pre-pass: f32 -> f16 convert
// ---------------------------------------------------------------------------
__global__ __launch_bounds__(256)
void f2h_kernel(const float* __restrict__ in, __half* __restrict__ out) {
    size_t i = (size_t)blockIdx.x * 256 + threadIdx.x;
    float4 v = ((const float4*)in)[i];
    uint2 o;
    o.x = pack_h2(v.x, v.y);
    o.y = pack_h2(v.z, v.w);
    ((uint2*)out)[i] = o;
}

// ---------------------------------------------------------------------------
// Pre-pass: transpose + convert: in [R][Cn] f32 -> out [Cn][R] f16
// ---------------------------------------------------------------------------
__global__ void trans_h_kernel(const float* __restrict__ in, __half* __restrict__ out,
                               int R, int Cn) {
    __shared__ float t[32][33];
    int bx = blockIdx.x * 32, by = blockIdx.y * 32;
    int tx = threadIdx.x, ty = threadIdx.y;   // (32, 8)
#pragma unroll
    for (int j = 0; j < 32; j += 8)
        t[ty + j][tx] = in[(size_t)(by + ty + j) * Cn + bx + tx];
    __syncthreads();
#pragma unroll
    for (int j = 0; j < 32; j += 8)
        out[(size_t)(bx + ty + j) * R + by + tx] = __float2half_rn(t[tx][ty + j]);
}

// ---------------------------------------------------------------------------
// fp16 GEMM:  C[M,N] = A[M,K]h @ Bt[N,K]h^T + bias[N]
// BM=BN=128, BK=32 halfs. 256 threads, 8 warps (4m x 2n), warp tile 32x64.
// cp.async 4-stage pipeline (3 chunks in flight) + ldmatrix fragments.
// smem rows: 16 u32 data + 4 pad (GROW=20) -> ldmatrix conflict-free.
// ---------------------------------------------------------------------------
#define GBM 128
#define GBN 128
#define GBK 32
#define GROW 20
#define G_TILE (128 * GROW)              // 2560 u32 per operand-stage
#define STAGES 4
#define GEMM_SMEM (2 * STAGES * G_TILE * 4)   // 81920 B

__global__ __launch_bounds__(256, 2)
void h_gemm_kernel(const __half* __restrict__ A, const __half* __restrict__ Bt,
                   const float* __restrict__ bias,
                   float* __restrict__ Cf, __half* __restrict__ Ch,
                   float* __restrict__ cache,
                   int M, int N, int K) {
    extern __shared__ uint32_t smu[];
    const uint32_t sbase = smem_u32(smu);
    const uint32_t sA = sbase;                            // [STAGES][G_TILE]
    const uint32_t sB = sbase + STAGES * G_TILE * 4;      // [STAGES][G_TILE]

    const int tid  = threadIdx.x;
    const int wid  = tid >> 5;
    const int lane = tid & 31;
    const int g    = lane >> 2;
    const int tg   = lane & 3;
    const int wm   = (wid & 3) * 32;
    const int wn   = (wid >> 2) * 64;
    const int m0   = blockIdx.y * GBM;
    const int n0   = blockIdx.x * GBN;
    const int rowu4 = K / 8;

    // cp.async coords: 2 chunks of 16B per operand per thread
    const uint4* gA[2]; const uint4* gB[2]; uint32_t so[2];
#pragma unroll
    for (int i = 0; i < 2; i++) {
        int idx = i * 256 + tid;
        int r = idx >> 2, c4 = idx & 3;
        gA[i] = (const uint4*)A + (size_t)(m0 + r) * rowu4 + c4;
        gB[i] = (const uint4*)Bt + (size_t)(n0 + r) * rowu4 + c4;
        so[i] = (uint32_t)(r * GROW + c4 * 4) * 4;
    }

    // ldmatrix lane addressing
    const int mrow = lane & 7;
    const int msel = lane >> 3;
    uint32_t aOff[2];
#pragma unroll
    for (int i = 0; i < 2; i++)
        aOff[i] = (uint32_t)(((wm + 16 * i + (msel & 1) * 8 + mrow) * GROW
                             + (msel >> 1) * 4) * 4);
    uint32_t bOff[4];
#pragma unroll
    for (int jj = 0; jj < 4; jj++)
        bOff[jj] = (uint32_t)(((wn + 16 * jj + (msel >> 1) * 8 + mrow) * GROW
                              + (msel & 1) * 4) * 4);

    float c[2][8][4];
#pragma unroll
    for (int i = 0; i < 2; i++)
#pragma unroll
        for (int j = 0; j < 8; j++)
#pragma unroll
            for (int q = 0; q < 4; q++) c[i][j][q] = 0.0f;

    const int NC = K / GBK;   // chunks

    // Prologue: issue stages 0, 1, 2
#pragma unroll
    for (int st = 0; st < 3; st++) {
        uint32_t aS = sA + st * G_TILE * 4;
        uint32_t bS = sB + st * G_TILE * 4;
#pragma unroll
        for (int i = 0; i < 2; i++) {
            cp16(aS + so[i], gA[i] + st * 4);
            cp16(bS + so[i], gB[i] + st * 4);
        }
        CP_COMMIT();
    }

    for (int ch = 0; ch < NC; ++ch) {
        // chunk ch must be complete; allowed outstanding groups =
        // min(3 + ch, NC) - (ch + 1)
        if (ch + 3 <= NC)      { CP_WAIT2(); }
        else if (ch + 2 <= NC) { CP_WAIT1(); }
        else                   { CP_WAIT0(); }
        __syncthreads();   // chunk ch visible; stage (ch+3)%4 free

        if (ch + 3 < NC) {
            int st = (ch + 3) % STAGES;
            uint32_t aS = sA + st * G_TILE * 4;
            uint32_t bS = sB + st * G_TILE * 4;
#pragma unroll
            for (int i = 0; i < 2; i++) {
                cp16(aS + so[i], gA[i] + (ch + 3) * 4);
                cp16(bS + so[i], gB[i] + (ch + 3) * 4);
            }
            CP_COMMIT();
        }

        const int cur = ch % STAGES;
        const uint32_t aS = sA + cur * G_TILE * 4;
        const uint32_t bS = sB + cur * G_TILE * 4;

#pragma unroll
        for (int s = 0; s < 2; s++) {
            uint32_t a[2][4], bq[4][4];
#pragma unroll
            for (int i = 0; i < 2; i++)
                ldsm_x4(a[i], aS + aOff[i] + s * 32);
#pragma unroll
            for (int jj = 0; jj < 4; jj++)
                ldsm_x4(bq[jj], bS + bOff[jj] + s * 32);
#pragma unroll
            for (int i = 0; i < 2; i++)
#pragma unroll
                for (int jj = 0; jj < 4; jj++) {
                    mma_h(c[i][2 * jj],     a[i], &bq[jj][0]);
                    mma_h(c[i][2 * jj + 1], a[i], &bq[jj][2]);
                }
        }
    }

    // Epilogue
#pragma unroll
    for (int i = 0; i < 2; i++) {
        int row = m0 + wm + 16 * i + g;
#pragma unroll
        for (int j = 0; j < 8; j++) {
            int col = n0 + wn + 8 * j + 2 * tg;
            float2 bv = *(const float2*)(bias + col);
            float2 o0, o1;
            o0.x = c[i][j][0] + bv.x;  o0.y = c[i][j][1] + bv.y;
            o1.x = c[i][j][2] + bv.x;  o1.y = c[i][j][3] + bv.y;
            if (Cf != nullptr) {
                *(float2*)(Cf + (size_t)row * N + col) = o0;
                *(float2*)(Cf + (size_t)(row + 8) * N + col) = o1;
            }
            if (Ch != nullptr) {
                *(uint32_t*)(Ch + (size_t)row * N + col) = pack_h2(o0.x, o0.y);
                *(uint32_t*)(Ch + (size_t)(row + 8) * N + col) = pack_h2(o1.x, o1.y);
            }
            if (cache != nullptr && col >= CC) {
                int cc = col - CC;
                *(float2*)(cache + (size_t)row * (2 * CC) + cc) = o0;
                *(float2*)(cache + (size_t)(row + 8) * (2 * CC) + cc) = o1;
            }
        }
    }
}

// ---------------------------------------------------------------------------
// Flash attention, fp16 mma (causal). Grid: (B*H, T/128). 256 threads.
// smem (u32): Qs[128][68], Ks[64][68], Vt[128][36], Ps[128][36]
// ---------------------------------------------------------------------------
#define AQW 68
#define AVW 36
#define ATTN_SMEM_U32 (128*AQW + 64*AQW + 128*AVW + 128*AVW)
#define ATTN_SMEM_BYTES (ATTN_SMEM_U32 * 4)

__global__ __launch_bounds__(256)
void attn_h_kernel(const __half* __restrict__ qkv, __half* __restrict__ y) {
    extern __shared__ uint32_t smu[];
    uint32_t* Qs = smu;                   // [128][68]
    uint32_t* Ks = Qs + 128 * AQW;        // [64][68]
    uint32_t* Vt = Ks + 64 * AQW;         // [128][36]
    uint32_t* Ps = Vt + 128 * AVW;        // [128][36]

    const int tid  = threadIdx.x;
    const int wid  = tid >> 5;
    const int lane = tid & 31;
    const int g    = lane >> 2;
    const int tg   = lane & 3;
    const int bh   = blockIdx.x;
    const int b    = bh >> 4;
    const int h    = bh & 15;
    const int qt   = gridDim.y - 1 - blockIdx.y;
    const int q0   = qt * 128;
    const int wr0  = wid * 16;

    const float SCALE = 0.08838834764831845f;
    const int ROWU4 = QKV_N / 8;          // 768

    const uint4* qkv4 = (const uint4*)qkv;
    const size_t bbase = (size_t)b * TT * ROWU4;
    const int qoff = h * 16;
    const int koff = 256 + h * 16;
    const int voff = 512 + h * 16;

#pragma unroll
    for (int p = 0; p < 8; p++) {
        int i = tid + 256 * p;
        int r = i >> 4, c4 = i & 15;
        uint4 v = qkv4[bbase + (size_t)(q0 + r) * ROWU4 + qoff + c4];
        *(uint4*)&Qs[r * AQW + c4 * 4] = v;
    }

    float m_prev[2] = {-1e30f, -1e30f};
    float l_acc[2]  = {0.0f, 0.0f};
    float acc[16][4];
#pragma unroll
    for (int nj = 0; nj < 16; nj++)
#pragma unroll
        for (int q = 0; q < 4; q++) acc[nj][q] = 0.0f;

    const int ntiles = 2 * qt + 2;

    for (int kt = 0; kt < ntiles; ++kt) {
        const int k0 = kt * 64;
        __syncthreads();

#pragma unroll
        for (int p = 0; p < 4; p++) {
            int i = tid + 256 * p;
            int r = i >> 4, c4 = i & 15;
            uint4 v = qkv4[bbase + (size_t)(k0 + r) * ROWU4 + koff + c4];
            *(uint4*)&Ks[r * AQW + c4 * 4] = v;
        }
#pragma unroll
        for (int p = 0; p < 2; p++) {
            int t = tid + 256 * p;
            int pr = t & 31;
            int dc = t >> 5;
            union { uint4 v; unsigned short s[8]; } ua, ub;
            ua.v = qkv4[bbase + (size_t)(k0 + 2 * pr)     * ROWU4 + voff + dc];
            ub.v = qkv4[bbase + (size_t)(k0 + 2 * pr + 1) * ROWU4 + voff + dc];
#pragma unroll
            for (int j = 0; j < 8; j++)
                Vt[(dc * 8 + j) * AVW + pr] =
                    (uint32_t)ua.s[j] | ((uint32_t)ub.s[j] << 16);
        }
        __syncthreads();

        float cs[8][4];
#pragma unroll
        for (int j = 0; j < 8; j++)
#pragma unroll
            for (int q = 0; q < 4; q++) cs[j][q] = 0.0f;

#pragma unroll
        for (int s = 0; s < 8; s++) {
            uint32_t a[4];
            a[0] = Qs[(wr0 + g)     * AQW + s * 8 + tg];
            a[1] = Qs[(wr0 + g + 8) * AQW + s * 8 + tg];
            a[2] = Qs[(wr0 + g)     * AQW + s * 8 + tg + 4];
            a[3] = Qs[(wr0 + g + 8) * AQW + s * 8 + tg + 4];
#pragma unroll
            for (int j = 0; j < 8; j++) {
                uint32_t bf[2];
                bf[0] = Ks[(8 * j + g) * AQW + s * 8 + tg];
                bf[1] = Ks[(8 * j + g) * AQW + s * 8 + tg + 4];
                mma_h(cs[j], a, bf);
            }
        }

        const int gr0 = q0 + wr0 + g;
        const int gr1 = gr0 + 8;
        float mx0 = -1e30f, mx1 = -1e30f;
#pragma unroll
        for (int j = 0; j < 8; j++) {
            int gc0 = k0 + 8 * j + 2 * tg;
            int gc1 = gc0 + 1;
            float s0 = cs[j][0] * SCALE; if (gc0 > gr0) s0 = -1e30f;
            float s1 = cs[j][1] * SCALE; if (gc1 > gr0) s1 = -1e30f;
            float s2 = cs[j][2] * SCALE; if (gc0 > gr1) s2 = -1e30f;
            float s3 = cs[j][3] * SCALE; if (gc1 > gr1) s3 = -1e30f;
            cs[j][0] = s0; cs[j][1] = s1; cs[j][2] = s2; cs[j][3] = s3;
            mx0 = fmaxf(mx0, fmaxf(s0, s1));
            mx1 = fmaxf(mx1, fmaxf(s2, s3));
        }
        mx0 = fmaxf(mx0, __shfl_xor_sync(0xffffffffu, mx0, 1));
        mx0 = fmaxf(mx0, __shfl_xor_sync(0xffffffffu, mx0, 2));
        mx1 = fmaxf(mx1, __shfl_xor_sync(0xffffffffu, mx1, 1));
        mx1 = fmaxf(mx1, __shfl_xor_sync(0xffffffffu, mx1, 2));

        float mn0 = fmaxf(m_prev[0], mx0);
        float mn1 = fmaxf(m_prev[1], mx1);
        float f0 = __expf(m_prev[0] - mn0);
        float f1 = __expf(m_prev[1] - mn1);
        m_prev[0] = mn0; m_prev[1] = mn1;

        float ls0 = 0.0f, ls1 = 0.0f;
#pragma unroll
        for (int j = 0; j < 8; j++) {
            float p0 = __expf(cs[j][0] - mn0);
            float p1 = __expf(cs[j][1] - mn0);
            float p2 = __expf(cs[j][2] - mn1);
            float p3 = __expf(cs[j][3] - mn1);
            ls0 += p0 + p1;
            ls1 += p2 + p3;
            Ps[(wr0 + g)     * AVW + 4 * j + tg] = pack_h2(p0, p1);
            Ps[(wr0 + g + 8) * AVW + 4 * j + tg] = pack_h2(p2, p3);
        }
        ls0 += __shfl_xor_sync(0xffffffffu, ls0, 1);
        ls0 += __shfl_xor_sync(0xffffffffu, ls0, 2);
        ls1 += __shfl_xor_sync(0xffffffffu, ls1, 1);
        ls1 += __shfl_xor_sync(0xffffffffu, ls1, 2);
        l_acc[0] = l_acc[0] * f0 + ls0;
        l_acc[1] = l_acc[1] * f1 + ls1;

#pragma unroll
        for (int nj = 0; nj < 16; nj++) {
            acc[nj][0] *= f0; acc[nj][1] *= f0;
            acc[nj][2] *= f1; acc[nj][3] *= f1;
        }
        __syncwarp();

#pragma unroll
        for (int s = 0; s < 4; s++) {
            uint32_t a[4];
            a[0] = Ps[(wr0 + g)     * AVW + s * 8 + tg];
            a[1] = Ps[(wr0 + g + 8) * AVW + s * 8 + tg];
            a[2] = Ps[(wr0 + g)     * AVW + s * 8 + tg + 4];
            a[3] = Ps[(wr0 + g + 8) * AVW + s * 8 + tg + 4];
#pragma unroll
            for (int nj = 0; nj < 16; nj++) {
                uint32_t bf[2];
                bf[0] = Vt[(8 * nj + g) * AVW + s * 8 + tg];
                bf[1] = Vt[(8 * nj + g) * AVW + s * 8 + tg + 4];
                mma_h(acc[nj], a, bf);
            }
        }
        __syncwarp();
    }

    float inv0 = 1.0f / l_acc[0];
    float inv1 = 1.0f / l_acc[1];
    size_t row0 = (size_t)(b * TT + q0 + wr0 + g);
    size_t row1 = row0 + 8;
#pragma unroll
    for (int nj = 0; nj < 16; nj++) {
        int col = h * DH + 8 * nj + 2 * tg;
        *(uint32_t*)(y + row0 * CC + col) = pack_h2(acc[nj][0] * inv0, acc[nj][1] * inv0);
        *(uint32_t*)(y + row1 * CC + col) = pack_h2(acc[nj][2] * inv1, acc[nj][3] * inv1);
    }
}

// ---------------------------------------------------------------------------
extern "C" void kernel_launch(void* const* d_in, const int* in_sizes, int n_in,
                              void* d_out, int out_size) {
    (void)in_sizes; (void)n_in; (void)out_size;
    const float* x      = (const float*)d_in[0];
    const float* W_attn = (const float*)d_in[2];
    const float* b_attn = (const float*)d_in[3];
    const float* W_proj = (const float*)d_in[4];
    const float* b_proj = (const float*)d_in[5];

    float* out   = (float*)d_out;
    float* y_out = out;
    float* cache = out + (size_t)M_ROWS * CC;

    __half *xh, *qkvh, *yh, *wath, *wpth;
    cudaGetSymbolAddress((void**)&xh,   g_xh);
    cudaGetSymbolAddress((void**)&qkvh, g_qkvh);
    cudaGetSymbolAddress((void**)&yh,   g_yh);
    cudaGetSymbolAddress((void**)&wath, g_wath);
    cudaGetSymbolAddress((void**)&wpth, g_wpth);

    cudaFuncSetAttribute(h_gemm_kernel,
                         cudaFuncAttributeMaxDynamicSharedMemorySize, GEMM_SMEM);
    cudaFuncSetAttribute(attn_h_kernel,
                         cudaFuncAttributeMaxDynamicSharedMemorySize, ATTN_SMEM_BYTES);

    // 0) pre-pass conversions
    f2h_kernel<<<(int)((size_t)M_ROWS * CC / 4 / 256), 256>>>(x, xh);
    {
        dim3 blk(32, 8);
        trans_h_kernel<<<dim3(QKV_N / 32, CC / 32), blk>>>(W_attn, wath, CC, QKV_N);
        trans_h_kernel<<<dim3(CC / 32, CC / 32), blk>>>(W_proj, wpth, CC, CC);
    }
    // 1) qkv = x @ W_attn + b_attn -> qkv fp16 + fused f32 cache
    {
        dim3 grid(QKV_N / GBN, M_ROWS / GBM);   // (48, 32)
        h_gemm_kernel<<<grid, 256, GEMM_SMEM>>>(xh, wath, b_attn,
                                                nullptr, qkvh, cache,
                                                M_ROWS, QKV_N, CC);
    }
    // 2) flash attention fp16 -> yh
    {
        dim3 grid(BB * HH, TT / 128);           // (32, 16)
        attn_h_kernel<<<grid, 256, ATTN_SMEM_BYTES>>>(qkvh, yh);
    }
    // 3) y = yh @ W_proj + b_proj -> f32 out
    {
        dim3 grid(CC / GBN, M_ROWS / GBM);      // (16, 32)
        h_gemm_kernel<<<grid, 256, GEMM_SMEM>>>(yh, wpth, b_proj,
                                                y_out, nullptr, nullptr,
                                                M_ROWS, CC, CC);
    }
}

// round 10
// speedup vs baseline: 1.1896x; 1.0733x over previous
#include <cuda_runtime.h>
#include <cuda_fp16.h>
#include <cstdint>
#include <cstddef>

// Problem constants
#define BB 2
#define TT 2048
#define CC 2048
#define HH 16
#define DH 128
#define M_ROWS (BB*TT)          // 4096
#define QKV_N  (3*CC)           // 6144

// Scratch (allocation-free rule: __device__ globals)
__device__ __half g_xh  [(size_t)M_ROWS * CC];      // x fp16        16 MB
__device__ __half g_qkvh[(size_t)M_ROWS * QKV_N];   // qkv fp16      48 MB
__device__ __half g_yh  [(size_t)M_ROWS * CC];      // attn out fp16 16 MB
__device__ __half g_wath[(size_t)QKV_N * CC];       // W_attn^T fp16 24 MB
__device__ __half g_wpth[(size_t)CC * CC];          // W_proj^T fp16  8 MB

// ---------------------------------------------------------------------------
// PTX helpers (all plain sm_80+)
// ---------------------------------------------------------------------------
__device__ __forceinline__ void mma_h(float* c, const uint32_t* a, const uint32_t* b) {
    asm volatile(
        "mma.sync.aligned.m16n8k16.row.col.f32.f16.f16.f32 "
        "{%0,%1,%2,%3}, {%4,%5,%6,%7}, {%8,%9}, {%0,%1,%2,%3};"
        : "+f"(c[0]), "+f"(c[1]), "+f"(c[2]), "+f"(c[3])
        : "r"(a[0]), "r"(a[1]), "r"(a[2]), "r"(a[3]), "r"(b[0]), "r"(b[1]));
}

__device__ __forceinline__ uint32_t pack_h2(float lo, float hi) {
    __half2 h = __floats2half2_rn(lo, hi);
    return *(uint32_t*)&h;
}

__device__ __forceinline__ uint32_t smem_u32(const void* p) {
    uint32_t a;
    asm("{ .reg .u64 t; cvta.to.shared.u64 t, %1; cvt.u32.u64 %0, t; }"
        : "=r"(a) : "l"(p));
    return a;
}

__device__ __forceinline__ void ldsm_x4(uint32_t* r, uint32_t addr) {
    asm volatile("ldmatrix.sync.aligned.m8n8.x4.shared.b16 {%0,%1,%2,%3}, [%4];"
                 : "=r"(r[0]), "=r"(r[1]), "=r"(r[2]), "=r"(r[3]) : "r"(addr));
}

__device__ __forceinline__ void ldsm_x4_t(uint32_t* r, uint32_t addr) {
    asm volatile("ldmatrix.sync.aligned.m8n8.x4.trans.shared.b16 {%0,%1,%2,%3}, [%4];"
                 : "=r"(r[0]), "=r"(r[1]), "=r"(r[2]), "=r"(r[3]) : "r"(addr));
}

__device__ __forceinline__ void cp16(uint32_t saddr, const void* gaddr) {
    asm volatile("cp.async.cg.shared.global [%0], [%1], 16;"
                 :: "r"(saddr), "l"(gaddr));
}
#define CP_COMMIT() asm volatile("cp.async.commit_group;" ::: "memory")
#define CP_WAIT2()  asm volatile("cp.async.wait_group 2;" ::: "memory")
#define CP_WAIT1()  asm volatile("cp.async.wait_group 1;" ::: "memory")
#define CP_WAIT0()  asm volatile("cp.async.wait_group 0;" ::: "memory")

// ---------------------------------------------------------------------------
// Pre-pass: f32 -> f16 convert
// ---------------------------------------------------------------------------
__global__ __launch_bounds__(256)
void f2h_kernel(const float* __restrict__ in, __half* __restrict__ out) {
    size_t i = (size_t)blockIdx.x * 256 + threadIdx.x;
    float4 v = ((const float4*)in)[i];
    uint2 o;
    o.x = pack_h2(v.x, v.y);
    o.y = pack_h2(v.z, v.w);
    ((uint2*)out)[i] = o;
}

// ---------------------------------------------------------------------------
// Pre-pass: transpose + convert: in [R][Cn] f32 -> out [Cn][R] f16
// ---------------------------------------------------------------------------
__global__ void trans_h_kernel(const float* __restrict__ in, __half* __restrict__ out,
                               int R, int Cn) {
    __shared__ float t[32][33];
    int bx = blockIdx.x * 32, by = blockIdx.y * 32;
    int tx = threadIdx.x, ty = threadIdx.y;   // (32, 8)
#pragma unroll
    for (int j = 0; j < 32; j += 8)
        t[ty + j][tx] = in[(size_t)(by + ty + j) * Cn + bx + tx];
    __syncthreads();
#pragma unroll
    for (int j = 0; j < 32; j += 8)
        out[(size_t)(bx + ty + j) * R + by + tx] = __float2half_rn(t[tx][ty + j]);
}

// ---------------------------------------------------------------------------
// fp16 GEMM (identical to R9 — protected win):
// BM=BN=128, BK=32, 256 thr, 4-stage cp.async, ldmatrix fragments.
// ---------------------------------------------------------------------------
#define GBM 128
#define GBN 128
#define GBK 32
#define GROW 20
#define G_TILE (128 * GROW)
#define STAGES 4
#define GEMM_SMEM (2 * STAGES * G_TILE * 4)   // 81920 B

__global__ __launch_bounds__(256, 2)
void h_gemm_kernel(const __half* __restrict__ A, const __half* __restrict__ Bt,
                   const float* __restrict__ bias,
                   float* __restrict__ Cf, __half* __restrict__ Ch,
                   float* __restrict__ cache,
                   int M, int N, int K) {
    extern __shared__ uint32_t smu[];
    const uint32_t sbase = smem_u32(smu);
    const uint32_t sA = sbase;
    const uint32_t sB = sbase + STAGES * G_TILE * 4;

    const int tid  = threadIdx.x;
    const int wid  = tid >> 5;
    const int lane = tid & 31;
    const int g    = lane >> 2;
    const int tg   = lane & 3;
    const int wm   = (wid & 3) * 32;
    const int wn   = (wid >> 2) * 64;
    const int m0   = blockIdx.y * GBM;
    const int n0   = blockIdx.x * GBN;
    const int rowu4 = K / 8;

    const uint4* gA[2]; const uint4* gB[2]; uint32_t so[2];
#pragma unroll
    for (int i = 0; i < 2; i++) {
        int idx = i * 256 + tid;
        int r = idx >> 2, c4 = idx & 3;
        gA[i] = (const uint4*)A + (size_t)(m0 + r) * rowu4 + c4;
        gB[i] = (const uint4*)Bt + (size_t)(n0 + r) * rowu4 + c4;
        so[i] = (uint32_t)(r * GROW + c4 * 4) * 4;
    }

    const int mrow = lane & 7;
    const int msel = lane >> 3;
    uint32_t aOff[2];
#pragma unroll
    for (int i = 0; i < 2; i++)
        aOff[i] = (uint32_t)(((wm + 16 * i + (msel & 1) * 8 + mrow) * GROW
                             + (msel >> 1) * 4) * 4);
    uint32_t bOff[4];
#pragma unroll
    for (int jj = 0; jj < 4; jj++)
        bOff[jj] = (uint32_t)(((wn + 16 * jj + (msel >> 1) * 8 + mrow) * GROW
                              + (msel & 1) * 4) * 4);

    float c[2][8][4];
#pragma unroll
    for (int i = 0; i < 2; i++)
#pragma unroll
        for (int j = 0; j < 8; j++)
#pragma unroll
            for (int q = 0; q < 4; q++) c[i][j][q] = 0.0f;

    const int NC = K / GBK;

#pragma unroll
    for (int st = 0; st < 3; st++) {
        uint32_t aS = sA + st * G_TILE * 4;
        uint32_t bS = sB + st * G_TILE * 4;
#pragma unroll
        for (int i = 0; i < 2; i++) {
            cp16(aS + so[i], gA[i] + st * 4);
            cp16(bS + so[i], gB[i] + st * 4);
        }
        CP_COMMIT();
    }

    for (int ch = 0; ch < NC; ++ch) {
        if (ch + 3 <= NC)      { CP_WAIT2(); }
        else if (ch + 2 <= NC) { CP_WAIT1(); }
        else                   { CP_WAIT0(); }
        __syncthreads();

        if (ch + 3 < NC) {
            int st = (ch + 3) % STAGES;
            uint32_t aS = sA + st * G_TILE * 4;
            uint32_t bS = sB + st * G_TILE * 4;
#pragma unroll
            for (int i = 0; i < 2; i++) {
                cp16(aS + so[i], gA[i] + (ch + 3) * 4);
                cp16(bS + so[i], gB[i] + (ch + 3) * 4);
            }
            CP_COMMIT();
        }

        const int cur = ch % STAGES;
        const uint32_t aS = sA + cur * G_TILE * 4;
        const uint32_t bS = sB + cur * G_TILE * 4;

#pragma unroll
        for (int s = 0; s < 2; s++) {
            uint32_t a[2][4], bq[4][4];
#pragma unroll
            for (int i = 0; i < 2; i++)
                ldsm_x4(a[i], aS + aOff[i] + s * 32);
#pragma unroll
            for (int jj = 0; jj < 4; jj++)
                ldsm_x4(bq[jj], bS + bOff[jj] + s * 32);
#pragma unroll
            for (int i = 0; i < 2; i++)
#pragma unroll
                for (int jj = 0; jj < 4; jj++) {
                    mma_h(c[i][2 * jj],     a[i], &bq[jj][0]);
                    mma_h(c[i][2 * jj + 1], a[i], &bq[jj][2]);
                }
        }
    }

#pragma unroll
    for (int i = 0; i < 2; i++) {
        int row = m0 + wm + 16 * i + g;
#pragma unroll
        for (int j = 0; j < 8; j++) {
            int col = n0 + wn + 8 * j + 2 * tg;
            float2 bv = *(const float2*)(bias + col);
            float2 o0, o1;
            o0.x = c[i][j][0] + bv.x;  o0.y = c[i][j][1] + bv.y;
            o1.x = c[i][j][2] + bv.x;  o1.y = c[i][j][3] + bv.y;
            if (Cf != nullptr) {
                *(float2*)(Cf + (size_t)row * N + col) = o0;
                *(float2*)(Cf + (size_t)(row + 8) * N + col) = o1;
            }
            if (Ch != nullptr) {
                *(uint32_t*)(Ch + (size_t)row * N + col) = pack_h2(o0.x, o0.y);
                *(uint32_t*)(Ch + (size_t)(row + 8) * N + col) = pack_h2(o1.x, o1.y);
            }
            if (cache != nullptr && col >= CC) {
                int cc = col - CC;
                *(float2*)(cache + (size_t)row * (2 * CC) + cc) = o0;
                *(float2*)(cache + (size_t)(row + 8) * (2 * CC) + cc) = o1;
            }
        }
    }
}

// ---------------------------------------------------------------------------
// Flash attention, fp16 mma (causal), ldmatrix fragments + trans-V.
// Grid: (B*H, T/128). 256 threads = 8 warps, warp = 16 q-rows x all 64 cols.
// smem (u32): Qs[128][68], Ks[64][68], Vs[64][68] (natural), Ps[128][36]
// ---------------------------------------------------------------------------
#define AQW 68
#define PW  36
#define ATTN_SMEM_U32 (128*AQW + 64*AQW + 64*AQW + 128*PW)
#define ATTN_SMEM_BYTES (ATTN_SMEM_U32 * 4)

__global__ __launch_bounds__(256, 2)
void attn_h_kernel(const __half* __restrict__ qkv, __half* __restrict__ y) {
    extern __shared__ uint32_t smu[];
    uint32_t* Qs = smu;                   // [128][68]
    uint32_t* Ks = Qs + 128 * AQW;        // [64][68]
    uint32_t* Vs = Ks + 64 * AQW;         // [64][68] natural [token][dim]
    uint32_t* Ps = Vs + 64 * AQW;         // [128][36]

    const uint32_t sbase = smem_u32(smu);
    const uint32_t sQ = sbase;
    const uint32_t sK = sbase + 128 * AQW * 4;
    const uint32_t sV = sK + 64 * AQW * 4;
    const uint32_t sP = sV + 64 * AQW * 4;

    const int tid  = threadIdx.x;
    const int wid  = tid >> 5;
    const int lane = tid & 31;
    const int g    = lane >> 2;
    const int tg   = lane & 3;
    const int bh   = blockIdx.x;
    const int b    = bh >> 4;
    const int h    = bh & 15;
    const int qt   = gridDim.y - 1 - blockIdx.y;
    const int q0   = qt * 128;
    const int wr0  = wid * 16;

    const float SCALE = 0.08838834764831845f;
    const int ROWU4 = QKV_N / 8;          // 768

    const uint4* qkv4 = (const uint4*)qkv;
    const size_t bbase = (size_t)b * TT * ROWU4;
    const int qoff = h * 16;
    const int koff = 256 + h * 16;
    const int voff = 512 + h * 16;

    // ldmatrix lane offsets
    const int mrow = lane & 7;
    const int msel = lane >> 3;
    // Q (A op): rows wr0..wr0+15
    const uint32_t qOff = (uint32_t)(((wr0 + (msel & 1) * 8 + mrow) * AQW
                                     + (msel >> 1) * 4) * 4);
    // K (B op, non-trans): rows 16jj..16jj+15
    uint32_t kOff[4];
#pragma unroll
    for (int jj = 0; jj < 4; jj++)
        kOff[jj] = (uint32_t)(((16 * jj + (msel >> 1) * 8 + mrow) * AQW
                              + (msel & 1) * 4) * 4);
    // P (A op): rows wr0..wr0+15, stride PW
    const uint32_t pOff = (uint32_t)(((wr0 + (msel & 1) * 8 + mrow) * PW
                                     + (msel >> 1) * 4) * 4);
    // V (B op, TRANS): k-rows (msel&1)*8+mrow, n-block 2v + (msel>>1)
    uint32_t vOff[8];
#pragma unroll
    for (int v = 0; v < 8; v++)
        vOff[v] = (uint32_t)((((msel & 1) * 8 + mrow) * AQW
                             + (2 * v + (msel >> 1)) * 4) * 4);

    // Load Q tile (128 rows x 16 uint4)
#pragma unroll
    for (int p = 0; p < 8; p++) {
        int i = tid + 256 * p;
        int r = i >> 4, c4 = i & 15;
        uint4 v = qkv4[bbase + (size_t)(q0 + r) * ROWU4 + qoff + c4];
        *(uint4*)&Qs[r * AQW + c4 * 4] = v;
    }

    float m_prev[2] = {-1e30f, -1e30f};
    float l_acc[2]  = {0.0f, 0.0f};
    float acc[16][4];
#pragma unroll
    for (int nj = 0; nj < 16; nj++)
#pragma unroll
        for (int q = 0; q < 4; q++) acc[nj][q] = 0.0f;

    const int ntiles = 2 * qt + 2;

    for (int kt = 0; kt < ntiles; ++kt) {
        const int k0 = kt * 64;
        __syncthreads();   // prior-iter K/V reads complete

        // K, V tiles: 64 rows x 16 uint4 each, natural layout
#pragma unroll
        for (int p = 0; p < 4; p++) {
            int i = tid + 256 * p;
            int r = i >> 4, c4 = i & 15;
            uint4 kv = qkv4[bbase + (size_t)(k0 + r) * ROWU4 + koff + c4];
            uint4 vv = qkv4[bbase + (size_t)(k0 + r) * ROWU4 + voff + c4];
            *(uint4*)&Ks[r * AQW + c4 * 4] = kv;
            *(uint4*)&Vs[r * AQW + c4 * 4] = vv;
        }
        __syncthreads();

        // ---- S = Q K^T : 16 x 64 per warp, ldmatrix fragments ----
        float cs[8][4];
#pragma unroll
        for (int j = 0; j < 8; j++)
#pragma unroll
            for (int q = 0; q < 4; q++) cs[j][q] = 0.0f;

#pragma unroll
        for (int s = 0; s < 8; s++) {
            uint32_t a[4], bq[4][4];
            ldsm_x4(a, sQ + qOff + s * 32);
#pragma unroll
            for (int jj = 0; jj < 4; jj++)
                ldsm_x4(bq[jj], sK + kOff[jj] + s * 32);
#pragma unroll
            for (int jj = 0; jj < 4; jj++) {
                mma_h(cs[2 * jj],     a, &bq[jj][0]);
                mma_h(cs[2 * jj + 1], a, &bq[jj][2]);
            }
        }

        // ---- scale + causal mask + row max ----
        const int gr0 = q0 + wr0 + g;
        const int gr1 = gr0 + 8;
        float mx0 = -1e30f, mx1 = -1e30f;
#pragma unroll
        for (int j = 0; j < 8; j++) {
            int gc0 = k0 + 8 * j + 2 * tg;
            int gc1 = gc0 + 1;
            float s0 = cs[j][0] * SCALE; if (gc0 > gr0) s0 = -1e30f;
            float s1 = cs[j][1] * SCALE; if (gc1 > gr0) s1 = -1e30f;
            float s2 = cs[j][2] * SCALE; if (gc0 > gr1) s2 = -1e30f;
            float s3 = cs[j][3] * SCALE; if (gc1 > gr1) s3 = -1e30f;
            cs[j][0] = s0; cs[j][1] = s1; cs[j][2] = s2; cs[j][3] = s3;
            mx0 = fmaxf(mx0, fmaxf(s0, s1));
            mx1 = fmaxf(mx1, fmaxf(s2, s3));
        }
        mx0 = fmaxf(mx0, __shfl_xor_sync(0xffffffffu, mx0, 1));
        mx0 = fmaxf(mx0, __shfl_xor_sync(0xffffffffu, mx0, 2));
        mx1 = fmaxf(mx1, __shfl_xor_sync(0xffffffffu, mx1, 1));
        mx1 = fmaxf(mx1, __shfl_xor_sync(0xffffffffu, mx1, 2));

        float mn0 = fmaxf(m_prev[0], mx0);
        float mn1 = fmaxf(m_prev[1], mx1);
        float f0 = __expf(m_prev[0] - mn0);
        float f1 = __expf(m_prev[1] - mn1);
        m_prev[0] = mn0; m_prev[1] = mn1;

        float ls0 = 0.0f, ls1 = 0.0f;
#pragma unroll
        for (int j = 0; j < 8; j++) {
            float p0 = __expf(cs[j][0] - mn0);
            float p1 = __expf(cs[j][1] - mn0);
            float p2 = __expf(cs[j][2] - mn1);
            float p3 = __expf(cs[j][3] - mn1);
            ls0 += p0 + p1;
            ls1 += p2 + p3;
            Ps[(wr0 + g)     * PW + 4 * j + tg] = pack_h2(p0, p1);
            Ps[(wr0 + g + 8) * PW + 4 * j + tg] = pack_h2(p2, p3);
        }
        ls0 += __shfl_xor_sync(0xffffffffu, ls0, 1);
        ls0 += __shfl_xor_sync(0xffffffffu, ls0, 2);
        ls1 += __shfl_xor_sync(0xffffffffu, ls1, 1);
        ls1 += __shfl_xor_sync(0xffffffffu, ls1, 2);
        l_acc[0] = l_acc[0] * f0 + ls0;
        l_acc[1] = l_acc[1] * f1 + ls1;

#pragma unroll
        for (int nj = 0; nj < 16; nj++) {
            acc[nj][0] *= f0; acc[nj][1] *= f0;
            acc[nj][2] *= f1; acc[nj][3] *= f1;
        }
        __syncwarp();   // P stores visible within warp

        // ---- acc += P @ V : ldmatrix A + trans-ldmatrix B from natural V ----
#pragma unroll
        for (int s = 0; s < 4; s++) {
            uint32_t a[4];
            ldsm_x4(a, sP + pOff + s * 32);
            const uint32_t vsbase = sV + (uint32_t)(s * 16 * AQW * 4);
#pragma unroll
            for (int v = 0; v < 8; v++) {
                uint32_t bq[4];
                ldsm_x4_t(bq, vsbase + vOff[v]);
                mma_h(acc[2 * v],     a, &bq[0]);
                mma_h(acc[2 * v + 1], a, &bq[2]);
            }
        }
        __syncwarp();   // P reads done before next-iter overwrite
    }

    float inv0 = 1.0f / l_acc[0];
    float inv1 = 1.0f / l_acc[1];
    size_t row0 = (size_t)(b * TT + q0 + wr0 + g);
    size_t row1 = row0 + 8;
#pragma unroll
    for (int nj = 0; nj < 16; nj++) {
        int col = h * DH + 8 * nj + 2 * tg;
        *(uint32_t*)(y + row0 * CC + col) = pack_h2(acc[nj][0] * inv0, acc[nj][1] * inv0);
        *(uint32_t*)(y + row1 * CC + col) = pack_h2(acc[nj][2] * inv1, acc[nj][3] * inv1);
    }
}

// ---------------------------------------------------------------------------
extern "C" void kernel_launch(void* const* d_in, const int* in_sizes, int n_in,
                              void* d_out, int out_size) {
    (void)in_sizes; (void)n_in; (void)out_size;
    const float* x      = (const float*)d_in[0];
    const float* W_attn = (const float*)d_in[2];
    const float* b_attn = (const float*)d_in[3];
    const float* W_proj = (const float*)d_in[4];
    const float* b_proj = (const float*)d_in[5];

    float* out   = (float*)d_out;
    float* y_out = out;
    float* cache = out + (size_t)M_ROWS * CC;

    __half *xh, *qkvh, *yh, *wath, *wpth;
    cudaGetSymbolAddress((void**)&xh,   g_xh);
    cudaGetSymbolAddress((void**)&qkvh, g_qkvh);
    cudaGetSymbolAddress((void**)&yh,   g_yh);
    cudaGetSymbolAddress((void**)&wath, g_wath);
    cudaGetSymbolAddress((void**)&wpth, g_wpth);

    cudaFuncSetAttribute(h_gemm_kernel,
                         cudaFuncAttributeMaxDynamicSharedMemorySize, GEMM_SMEM);
    cudaFuncSetAttribute(attn_h_kernel,
                         cudaFuncAttributeMaxDynamicSharedMemorySize, ATTN_SMEM_BYTES);

    // 0) pre-pass conversions
    f2h_kernel<<<(int)((size_t)M_ROWS * CC / 4 / 256), 256>>>(x, xh);
    {
        dim3 blk(32, 8);
        trans_h_kernel<<<dim3(QKV_N / 32, CC / 32), blk>>>(W_attn, wath, CC, QKV_N);
        trans_h_kernel<<<dim3(CC / 32, CC / 32), blk>>>(W_proj, wpth, CC, CC);
    }
    // 1) qkv = x @ W_attn + b_attn -> qkv fp16 + fused f32 cache
    {
        dim3 grid(QKV_N / GBN, M_ROWS / GBM);   // (48, 32)
        h_gemm_kernel<<<grid, 256, GEMM_SMEM>>>(xh, wath, b_attn,
                                                nullptr, qkvh, cache,
                                                M_ROWS, QKV_N, CC);
    }
    // 2) flash attention fp16 -> yh
    {
        dim3 grid(BB * HH, TT / 128);           // (32, 16)
        attn_h_kernel<<<grid, 256, ATTN_SMEM_BYTES>>>(qkvh, yh);
    }
    // 3) y = yh @ W_proj + b_proj -> f32 out
    {
        dim3 grid(CC / GBN, M_ROWS / GBM);      // (16, 32)
        h_gemm_kernel<<<grid, 256, GEMM_SMEM>>>(yh, wpth, b_proj,
                                                y_out, nullptr, nullptr,
                                                M_ROWS, CC, CC);
    }
}

// round 11
// speedup vs baseline: 1.2859x; 1.0810x over previous
#include <cuda_runtime.h>
#include <cuda_fp16.h>
#include <cstdint>
#include <cstddef>

// Problem constants
#define BB 2
#define TT 2048
#define CC 2048
#define HH 16
#define DH 128
#define M_ROWS (BB*TT)          // 4096
#define QKV_N  (3*CC)           // 6144

// Scratch (allocation-free rule: __device__ globals)
__device__ __half g_xh  [(size_t)M_ROWS * CC];      // x fp16        16 MB
__device__ __half g_qkvh[(size_t)M_ROWS * QKV_N];   // qkv fp16      48 MB
__device__ __half g_yh  [(size_t)M_ROWS * CC];      // attn out fp16 16 MB
__device__ __half g_wath[(size_t)QKV_N * CC];       // W_attn^T fp16 24 MB
__device__ __half g_wpth[(size_t)CC * CC];          // W_proj^T fp16  8 MB

// ---------------------------------------------------------------------------
// PTX helpers (all plain sm_80+)
// ---------------------------------------------------------------------------
__device__ __forceinline__ void mma_h(float* c, const uint32_t* a, const uint32_t* b) {
    asm volatile(
        "mma.sync.aligned.m16n8k16.row.col.f32.f16.f16.f32 "
        "{%0,%1,%2,%3}, {%4,%5,%6,%7}, {%8,%9}, {%0,%1,%2,%3};"
        : "+f"(c[0]), "+f"(c[1]), "+f"(c[2]), "+f"(c[3])
        : "r"(a[0]), "r"(a[1]), "r"(a[2]), "r"(a[3]), "r"(b[0]), "r"(b[1]));
}

__device__ __forceinline__ uint32_t pack_h2(float lo, float hi) {
    __half2 h = __floats2half2_rn(lo, hi);
    return *(uint32_t*)&h;
}

__device__ __forceinline__ uint32_t smem_u32(const void* p) {
    uint32_t a;
    asm("{ .reg .u64 t; cvta.to.shared.u64 t, %1; cvt.u32.u64 %0, t; }"
        : "=r"(a) : "l"(p));
    return a;
}

__device__ __forceinline__ void ldsm_x4(uint32_t* r, uint32_t addr) {
    asm volatile("ldmatrix.sync.aligned.m8n8.x4.shared.b16 {%0,%1,%2,%3}, [%4];"
                 : "=r"(r[0]), "=r"(r[1]), "=r"(r[2]), "=r"(r[3]) : "r"(addr));
}

__device__ __forceinline__ void ldsm_x4_t(uint32_t* r, uint32_t addr) {
    asm volatile("ldmatrix.sync.aligned.m8n8.x4.trans.shared.b16 {%0,%1,%2,%3}, [%4];"
                 : "=r"(r[0]), "=r"(r[1]), "=r"(r[2]), "=r"(r[3]) : "r"(addr));
}

__device__ __forceinline__ void cp16(uint32_t saddr, const void* gaddr) {
    asm volatile("cp.async.cg.shared.global [%0], [%1], 16;"
                 :: "r"(saddr), "l"(gaddr));
}
#define CP_COMMIT() asm volatile("cp.async.commit_group;" ::: "memory")
#define CP_WAIT1()  asm volatile("cp.async.wait_group 1;" ::: "memory")
#define CP_WAIT0()  asm volatile("cp.async.wait_group 0;" ::: "memory")

// ---------------------------------------------------------------------------
// Pre-pass: f32 -> f16 convert
// ---------------------------------------------------------------------------
__global__ __launch_bounds__(256)
void f2h_kernel(const float* __restrict__ in, __half* __restrict__ out) {
    size_t i = (size_t)blockIdx.x * 256 + threadIdx.x;
    float4 v = ((const float4*)in)[i];
    uint2 o;
    o.x = pack_h2(v.x, v.y);
    o.y = pack_h2(v.z, v.w);
    ((uint2*)out)[i] = o;
}

// ---------------------------------------------------------------------------
// Pre-pass: transpose + convert: in [R][Cn] f32 -> out [Cn][R] f16
// ---------------------------------------------------------------------------
__global__ void trans_h_kernel(const float* __restrict__ in, __half* __restrict__ out,
                               int R, int Cn) {
    __shared__ float t[32][33];
    int bx = blockIdx.x * 32, by = blockIdx.y * 32;
    int tx = threadIdx.x, ty = threadIdx.y;   // (32, 8)
#pragma unroll
    for (int j = 0; j < 32; j += 8)
        t[ty + j][tx] = in[(size_t)(by + ty + j) * Cn + bx + tx];
    __syncthreads();
#pragma unroll
    for (int j = 0; j < 32; j += 8)
        out[(size_t)(bx + ty + j) * R + by + tx] = __float2half_rn(t[tx][ty + j]);
}

// ---------------------------------------------------------------------------
// fp16 GEMM:  C[M,N] = A[M,K]h @ Bt[N,K]h^T + bias[N]
// BM=BN=128, BK=64 halfs. 256 threads, 8 warps (4m x 2n), warp tile 32x64.
// cp.async 3-stage pipeline + ldmatrix fragments. One barrier per 64 MMA.
// smem rows: 32 u32 data + 4 pad (AROW=36) -> conflict-free (validated).
// ---------------------------------------------------------------------------
#define GBM 128
#define GBN 128
#define GBK 64
#define AROW 36
#define G_TILE (128 * AROW)              // 4608 u32 per operand-stage
#define STAGES 3
#define GEMM_SMEM (2 * STAGES * G_TILE * 4)   // 110592 B

__global__ __launch_bounds__(256, 2)
void h_gemm_kernel(const __half* __restrict__ A, const __half* __restrict__ Bt,
                   const float* __restrict__ bias,
                   float* __restrict__ Cf, __half* __restrict__ Ch,
                   float* __restrict__ cache,
                   int M, int N, int K) {
    extern __shared__ uint32_t smu[];
    const uint32_t sbase = smem_u32(smu);
    const uint32_t sA = sbase;                            // [STAGES][G_TILE]
    const uint32_t sB = sbase + STAGES * G_TILE * 4;      // [STAGES][G_TILE]

    const int tid  = threadIdx.x;
    const int wid  = tid >> 5;
    const int lane = tid & 31;
    const int g    = lane >> 2;
    const int tg   = lane & 3;
    const int wm   = (wid & 3) * 32;
    const int wn   = (wid >> 2) * 64;
    const int m0   = blockIdx.y * GBM;
    const int n0   = blockIdx.x * GBN;
    const int rowu4 = K / 8;

    // cp.async coords: 4 chunks of 16B per operand per thread per stage
    const uint4* gA[4]; const uint4* gB[4]; uint32_t so[4];
#pragma unroll
    for (int i = 0; i < 4; i++) {
        int idx = i * 256 + tid;
        int r = idx >> 3, c4 = idx & 7;
        gA[i] = (const uint4*)A + (size_t)(m0 + r) * rowu4 + c4;
        gB[i] = (const uint4*)Bt + (size_t)(n0 + r) * rowu4 + c4;
        so[i] = (uint32_t)(r * AROW + c4 * 4) * 4;
    }

    // ldmatrix lane addressing
    const int mrow = lane & 7;
    const int msel = lane >> 3;
    uint32_t aOff[2];
#pragma unroll
    for (int i = 0; i < 2; i++)
        aOff[i] = (uint32_t)(((wm + 16 * i + (msel & 1) * 8 + mrow) * AROW
                             + (msel >> 1) * 4) * 4);
    uint32_t bOff[4];
#pragma unroll
    for (int jj = 0; jj < 4; jj++)
        bOff[jj] = (uint32_t)(((wn + 16 * jj + (msel >> 1) * 8 + mrow) * AROW
                              + (msel & 1) * 4) * 4);

    float c[2][8][4];
#pragma unroll
    for (int i = 0; i < 2; i++)
#pragma unroll
        for (int j = 0; j < 8; j++)
#pragma unroll
            for (int q = 0; q < 4; q++) c[i][j][q] = 0.0f;

    const int NC = K / GBK;   // 32 chunks

    // Prologue: issue stages 0, 1
#pragma unroll
    for (int st = 0; st < 2; st++) {
        uint32_t aS = sA + st * G_TILE * 4;
        uint32_t bS = sB + st * G_TILE * 4;
#pragma unroll
        for (int i = 0; i < 4; i++) {
            cp16(aS + so[i], gA[i] + st * 8);
            cp16(bS + so[i], gB[i] + st * 8);
        }
        CP_COMMIT();
    }

    for (int ch = 0; ch < NC; ++ch) {
        if (ch + 1 < NC) { CP_WAIT1(); } else { CP_WAIT0(); }
        __syncthreads();   // chunk ch visible; stage (ch+2)%3 free

        if (ch + 2 < NC) {
            int st = (ch + 2) % STAGES;
            uint32_t aS = sA + st * G_TILE * 4;
            uint32_t bS = sB + st * G_TILE * 4;
#pragma unroll
            for (int i = 0; i < 4; i++) {
                cp16(aS + so[i], gA[i] + (ch + 2) * 8);
                cp16(bS + so[i], gB[i] + (ch + 2) * 8);
            }
            CP_COMMIT();
        }

        const int cur = ch % STAGES;
        const uint32_t aS = sA + cur * G_TILE * 4;
        const uint32_t bS = sB + cur * G_TILE * 4;

#pragma unroll
        for (int s = 0; s < 4; s++) {
            uint32_t a[2][4], bq[4][4];
#pragma unroll
            for (int i = 0; i < 2; i++)
                ldsm_x4(a[i], aS + aOff[i] + s * 32);
#pragma unroll
            for (int jj = 0; jj < 4; jj++)
                ldsm_x4(bq[jj], bS + bOff[jj] + s * 32);
#pragma unroll
            for (int i = 0; i < 2; i++)
#pragma unroll
                for (int jj = 0; jj < 4; jj++) {
                    mma_h(c[i][2 * jj],     a[i], &bq[jj][0]);
                    mma_h(c[i][2 * jj + 1], a[i], &bq[jj][2]);
                }
        }
    }

    // Epilogue
#pragma unroll
    for (int i = 0; i < 2; i++) {
        int row = m0 + wm + 16 * i + g;
#pragma unroll
        for (int j = 0; j < 8; j++) {
            int col = n0 + wn + 8 * j + 2 * tg;
            float2 bv = *(const float2*)(bias + col);
            float2 o0, o1;
            o0.x = c[i][j][0] + bv.x;  o0.y = c[i][j][1] + bv.y;
            o1.x = c[i][j][2] + bv.x;  o1.y = c[i][j][3] + bv.y;
            if (Cf != nullptr) {
                *(float2*)(Cf + (size_t)row * N + col) = o0;
                *(float2*)(Cf + (size_t)(row + 8) * N + col) = o1;
            }
            if (Ch != nullptr) {
                *(uint32_t*)(Ch + (size_t)row * N + col) = pack_h2(o0.x, o0.y);
                *(uint32_t*)(Ch + (size_t)(row + 8) * N + col) = pack_h2(o1.x, o1.y);
            }
            if (cache != nullptr && col >= CC) {
                int cc = col - CC;
                *(float2*)(cache + (size_t)row * (2 * CC) + cc) = o0;
                *(float2*)(cache + (size_t)(row + 8) * (2 * CC) + cc) = o1;
            }
        }
    }
}

// ---------------------------------------------------------------------------
// Flash attention, fp16 mma (causal), ldmatrix fragments + trans-V.
// (byte-identical to R10 — protected win)
// ---------------------------------------------------------------------------
#define AQW 68
#define PW  36
#define ATTN_SMEM_U32 (128*AQW + 64*AQW + 64*AQW + 128*PW)
#define ATTN_SMEM_BYTES (ATTN_SMEM_U32 * 4)

__global__ __launch_bounds__(256, 2)
void attn_h_kernel(const __half* __restrict__ qkv, __half* __restrict__ y) {
    extern __shared__ uint32_t smu[];
    uint32_t* Qs = smu;                   // [128][68]
    uint32_t* Ks = Qs + 128 * AQW;        // [64][68]
    uint32_t* Vs = Ks + 64 * AQW;         // [64][68] natural [token][dim]
    uint32_t* Ps = Vs + 64 * AQW;         // [128][36]

    const uint32_t sbase = smem_u32(smu);
    const uint32_t sQ = sbase;
    const uint32_t sK = sbase + 128 * AQW * 4;
    const uint32_t sV = sK + 64 * AQW * 4;
    const uint32_t sP = sV + 64 * AQW * 4;

    const int tid  = threadIdx.x;
    const int wid  = tid >> 5;
    const int lane = tid & 31;
    const int g    = lane >> 2;
    const int tg   = lane & 3;
    const int bh   = blockIdx.x;
    const int b    = bh >> 4;
    const int h    = bh & 15;
    const int qt   = gridDim.y - 1 - blockIdx.y;
    const int q0   = qt * 128;
    const int wr0  = wid * 16;

    const float SCALE = 0.08838834764831845f;
    const int ROWU4 = QKV_N / 8;          // 768

    const uint4* qkv4 = (const uint4*)qkv;
    const size_t bbase = (size_t)b * TT * ROWU4;
    const int qoff = h * 16;
    const int koff = 256 + h * 16;
    const int voff = 512 + h * 16;

    const int mrow = lane & 7;
    const int msel = lane >> 3;
    const uint32_t qOff = (uint32_t)(((wr0 + (msel & 1) * 8 + mrow) * AQW
                                     + (msel >> 1) * 4) * 4);
    uint32_t kOff[4];
#pragma unroll
    for (int jj = 0; jj < 4; jj++)
        kOff[jj] = (uint32_t)(((16 * jj + (msel >> 1) * 8 + mrow) * AQW
                              + (msel & 1) * 4) * 4);
    const uint32_t pOff = (uint32_t)(((wr0 + (msel & 1) * 8 + mrow) * PW
                                     + (msel >> 1) * 4) * 4);
    uint32_t vOff[8];
#pragma unroll
    for (int v = 0; v < 8; v++)
        vOff[v] = (uint32_t)((((msel & 1) * 8 + mrow) * AQW
                             + (2 * v + (msel >> 1)) * 4) * 4);

#pragma unroll
    for (int p = 0; p < 8; p++) {
        int i = tid + 256 * p;
        int r = i >> 4, c4 = i & 15;
        uint4 v = qkv4[bbase + (size_t)(q0 + r) * ROWU4 + qoff + c4];
        *(uint4*)&Qs[r * AQW + c4 * 4] = v;
    }

    float m_prev[2] = {-1e30f, -1e30f};
    float l_acc[2]  = {0.0f, 0.0f};
    float acc[16][4];
#pragma unroll
    for (int nj = 0; nj < 16; nj++)
#pragma unroll
        for (int q = 0; q < 4; q++) acc[nj][q] = 0.0f;

    const int ntiles = 2 * qt + 2;

    for (int kt = 0; kt < ntiles; ++kt) {
        const int k0 = kt * 64;
        __syncthreads();

#pragma unroll
        for (int p = 0; p < 4; p++) {
            int i = tid + 256 * p;
            int r = i >> 4, c4 = i & 15;
            uint4 kv = qkv4[bbase + (size_t)(k0 + r) * ROWU4 + koff + c4];
            uint4 vv = qkv4[bbase + (size_t)(k0 + r) * ROWU4 + voff + c4];
            *(uint4*)&Ks[r * AQW + c4 * 4] = kv;
            *(uint4*)&Vs[r * AQW + c4 * 4] = vv;
        }
        __syncthreads();

        float cs[8][4];
#pragma unroll
        for (int j = 0; j < 8; j++)
#pragma unroll
            for (int q = 0; q < 4; q++) cs[j][q] = 0.0f;

#pragma unroll
        for (int s = 0; s < 8; s++) {
            uint32_t a[4], bq[4][4];
            ldsm_x4(a, sQ + qOff + s * 32);
#pragma unroll
            for (int jj = 0; jj < 4; jj++)
                ldsm_x4(bq[jj], sK + kOff[jj] + s * 32);
#pragma unroll
            for (int jj = 0; jj < 4; jj++) {
                mma_h(cs[2 * jj],     a, &bq[jj][0]);
                mma_h(cs[2 * jj + 1], a, &bq[jj][2]);
            }
        }

        const int gr0 = q0 + wr0 + g;
        const int gr1 = gr0 + 8;
        float mx0 = -1e30f, mx1 = -1e30f;
#pragma unroll
        for (int j = 0; j < 8; j++) {
            int gc0 = k0 + 8 * j + 2 * tg;
            int gc1 = gc0 + 1;
            float s0 = cs[j][0] * SCALE; if (gc0 > gr0) s0 = -1e30f;
            float s1 = cs[j][1] * SCALE; if (gc1 > gr0) s1 = -1e30f;
            float s2 = cs[j][2] * SCALE; if (gc0 > gr1) s2 = -1e30f;
            float s3 = cs[j][3] * SCALE; if (gc1 > gr1) s3 = -1e30f;
            cs[j][0] = s0; cs[j][1] = s1; cs[j][2] = s2; cs[j][3] = s3;
            mx0 = fmaxf(mx0, fmaxf(s0, s1));
            mx1 = fmaxf(mx1, fmaxf(s2, s3));
        }
        mx0 = fmaxf(mx0, __shfl_xor_sync(0xffffffffu, mx0, 1));
        mx0 = fmaxf(mx0, __shfl_xor_sync(0xffffffffu, mx0, 2));
        mx1 = fmaxf(mx1, __shfl_xor_sync(0xffffffffu, mx1, 1));
        mx1 = fmaxf(mx1, __shfl_xor_sync(0xffffffffu, mx1, 2));

        float mn0 = fmaxf(m_prev[0], mx0);
        float mn1 = fmaxf(m_prev[1], mx1);
        float f0 = __expf(m_prev[0] - mn0);
        float f1 = __expf(m_prev[1] - mn1);
        m_prev[0] = mn0; m_prev[1] = mn1;

        float ls0 = 0.0f, ls1 = 0.0f;
#pragma unroll
        for (int j = 0; j < 8; j++) {
            float p0 = __expf(cs[j][0] - mn0);
            float p1 = __expf(cs[j][1] - mn0);
            float p2 = __expf(cs[j][2] - mn1);
            float p3 = __expf(cs[j][3] - mn1);
            ls0 += p0 + p1;
            ls1 += p2 + p3;
            Ps[(wr0 + g)     * PW + 4 * j + tg] = pack_h2(p0, p1);
            Ps[(wr0 + g + 8) * PW + 4 * j + tg] = pack_h2(p2, p3);
        }
        ls0 += __shfl_xor_sync(0xffffffffu, ls0, 1);
        ls0 += __shfl_xor_sync(0xffffffffu, ls0, 2);
        ls1 += __shfl_xor_sync(0xffffffffu, ls1, 1);
        ls1 += __shfl_xor_sync(0xffffffffu, ls1, 2);
        l_acc[0] = l_acc[0] * f0 + ls0;
        l_acc[1] = l_acc[1] * f1 + ls1;

#pragma unroll
        for (int nj = 0; nj < 16; nj++) {
            acc[nj][0] *= f0; acc[nj][1] *= f0;
            acc[nj][2] *= f1; acc[nj][3] *= f1;
        }
        __syncwarp();

#pragma unroll
        for (int s = 0; s < 4; s++) {
            uint32_t a[4];
            ldsm_x4(a, sP + pOff + s * 32);
            const uint32_t vsbase = sV + (uint32_t)(s * 16 * AQW * 4);
#pragma unroll
            for (int v = 0; v < 8; v++) {
                uint32_t bq[4];
                ldsm_x4_t(bq, vsbase + vOff[v]);
                mma_h(acc[2 * v],     a, &bq[0]);
                mma_h(acc[2 * v + 1], a, &bq[2]);
            }
        }
        __syncwarp();
    }

    float inv0 = 1.0f / l_acc[0];
    float inv1 = 1.0f / l_acc[1];
    size_t row0 = (size_t)(b * TT + q0 + wr0 + g);
    size_t row1 = row0 + 8;
#pragma unroll
    for (int nj = 0; nj < 16; nj++) {
        int col = h * DH + 8 * nj + 2 * tg;
        *(uint32_t*)(y + row0 * CC + col) = pack_h2(acc[nj][0] * inv0, acc[nj][1] * inv0);
        *(uint32_t*)(y + row1 * CC + col) = pack_h2(acc[nj][2] * inv1, acc[nj][3] * inv1);
    }
}

// ---------------------------------------------------------------------------
extern "C" void kernel_launch(void* const* d_in, const int* in_sizes, int n_in,
                              void* d_out, int out_size) {
    (void)in_sizes; (void)n_in; (void)out_size;
    const float* x      = (const float*)d_in[0];
    const float* W_attn = (const float*)d_in[2];
    const float* b_attn = (const float*)d_in[3];
    const float* W_proj = (const float*)d_in[4];
    const float* b_proj = (const float*)d_in[5];

    float* out   = (float*)d_out;
    float* y_out = out;
    float* cache = out + (size_t)M_ROWS * CC;

    __half *xh, *qkvh, *yh, *wath, *wpth;
    cudaGetSymbolAddress((void**)&xh,   g_xh);
    cudaGetSymbolAddress((void**)&qkvh, g_qkvh);
    cudaGetSymbolAddress((void**)&yh,   g_yh);
    cudaGetSymbolAddress((void**)&wath, g_wath);
    cudaGetSymbolAddress((void**)&wpth, g_wpth);

    cudaFuncSetAttribute(h_gemm_kernel,
                         cudaFuncAttributeMaxDynamicSharedMemorySize, GEMM_SMEM);
    cudaFuncSetAttribute(attn_h_kernel,
                         cudaFuncAttributeMaxDynamicSharedMemorySize, ATTN_SMEM_BYTES);

    // 0) pre-pass conversions
    f2h_kernel<<<(int)((size_t)M_ROWS * CC / 4 / 256), 256>>>(x, xh);
    {
        dim3 blk(32, 8);
        trans_h_kernel<<<dim3(QKV_N / 32, CC / 32), blk>>>(W_attn, wath, CC, QKV_N);
        trans_h_kernel<<<dim3(CC / 32, CC / 32), blk>>>(W_proj, wpth, CC, CC);
    }
    // 1) qkv = x @ W_attn + b_attn -> qkv fp16 + fused f32 cache
    {
        dim3 grid(QKV_N / GBN, M_ROWS / GBM);   // (48, 32)
        h_gemm_kernel<<<grid, 256, GEMM_SMEM>>>(xh, wath, b_attn,
                                                nullptr, qkvh, cache,
                                                M_ROWS, QKV_N, CC);
    }
    // 2) flash attention fp16 -> yh
    {
        dim3 grid(BB * HH, TT / 128);           // (32, 16)
        attn_h_kernel<<<grid, 256, ATTN_SMEM_BYTES>>>(qkvh, yh);
    }
    // 3) y = yh @ W_proj + b_proj -> f32 out
    {
        dim3 grid(CC / GBN, M_ROWS / GBM);      // (16, 32)
        h_gemm_kernel<<<grid, 256, GEMM_SMEM>>>(yh, wpth, b_proj,
                                                y_out, nullptr, nullptr,
                                                M_ROWS, CC, CC);
    }
}

// round 12
// speedup vs baseline: 1.3039x; 1.0140x over previous
#include <cuda_runtime.h>
#include <cuda_fp16.h>
#include <cstdint>
#include <cstddef>

// Problem constants
#define BB 2
#define TT 2048
#define CC 2048
#define HH 16
#define DH 128
#define M_ROWS (BB*TT)          // 4096
#define QKV_N  (3*CC)           // 6144

// Scratch (allocation-free rule: __device__ globals)
__device__ __half g_xh  [(size_t)M_ROWS * CC];      // x fp16        16 MB
__device__ __half g_qkvh[(size_t)M_ROWS * QKV_N];   // qkv fp16      48 MB
__device__ __half g_yh  [(size_t)M_ROWS * CC];      // attn out fp16 16 MB
__device__ __half g_wath[(size_t)QKV_N * CC];       // W_attn^T fp16 24 MB
__device__ __half g_wpth[(size_t)CC * CC];          // W_proj^T fp16  8 MB

// ---------------------------------------------------------------------------
// PTX helpers (all plain sm_80+)
// ---------------------------------------------------------------------------
__device__ __forceinline__ void mma_h(float* c, const uint32_t* a, const uint32_t* b) {
    asm volatile(
        "mma.sync.aligned.m16n8k16.row.col.f32.f16.f16.f32 "
        "{%0,%1,%2,%3}, {%4,%5,%6,%7}, {%8,%9}, {%0,%1,%2,%3};"
        : "+f"(c[0]), "+f"(c[1]), "+f"(c[2]), "+f"(c[3])
        : "r"(a[0]), "r"(a[1]), "r"(a[2]), "r"(a[3]), "r"(b[0]), "r"(b[1]));
}

__device__ __forceinline__ uint32_t pack_h2(float lo, float hi) {
    __half2 h = __floats2half2_rn(lo, hi);
    return *(uint32_t*)&h;
}

__device__ __forceinline__ uint32_t smem_u32(const void* p) {
    uint32_t a;
    asm("{ .reg .u64 t; cvta.to.shared.u64 t, %1; cvt.u32.u64 %0, t; }"
        : "=r"(a) : "l"(p));
    return a;
}

__device__ __forceinline__ void ldsm_x4(uint32_t* r, uint32_t addr) {
    asm volatile("ldmatrix.sync.aligned.m8n8.x4.shared.b16 {%0,%1,%2,%3}, [%4];"
                 : "=r"(r[0]), "=r"(r[1]), "=r"(r[2]), "=r"(r[3]) : "r"(addr));
}

__device__ __forceinline__ void ldsm_x4_t(uint32_t* r, uint32_t addr) {
    asm volatile("ldmatrix.sync.aligned.m8n8.x4.trans.shared.b16 {%0,%1,%2,%3}, [%4];"
                 : "=r"(r[0]), "=r"(r[1]), "=r"(r[2]), "=r"(r[3]) : "r"(addr));
}

__device__ __forceinline__ void cp16(uint32_t saddr, const void* gaddr) {
    asm volatile("cp.async.cg.shared.global [%0], [%1], 16;"
                 :: "r"(saddr), "l"(gaddr));
}
#define CP_COMMIT() asm volatile("cp.async.commit_group;" ::: "memory")
#define CP_WAIT1()  asm volatile("cp.async.wait_group 1;" ::: "memory")
#define CP_WAIT0()  asm volatile("cp.async.wait_group 0;" ::: "memory")

// ---------------------------------------------------------------------------
// Pre-pass: f32 -> f16 convert
// ---------------------------------------------------------------------------
__global__ __launch_bounds__(256)
void f2h_kernel(const float* __restrict__ in, __half* __restrict__ out) {
    size_t i = (size_t)blockIdx.x * 256 + threadIdx.x;
    float4 v = ((const float4*)in)[i];
    uint2 o;
    o.x = pack_h2(v.x, v.y);
    o.y = pack_h2(v.z, v.w);
    ((uint2*)out)[i] = o;
}

// ---------------------------------------------------------------------------
// Pre-pass: transpose + convert: in [R][Cn] f32 -> out [Cn][R] f16
// ---------------------------------------------------------------------------
__global__ void trans_h_kernel(const float* __restrict__ in, __half* __restrict__ out,
                               int R, int Cn) {
    __shared__ float t[32][33];
    int bx = blockIdx.x * 32, by = blockIdx.y * 32;
    int tx = threadIdx.x, ty = threadIdx.y;   // (32, 8)
#pragma unroll
    for (int j = 0; j < 32; j += 8)
        t[ty + j][tx] = in[(size_t)(by + ty + j) * Cn + bx + tx];
    __syncthreads();
#pragma unroll
    for (int j = 0; j < 32; j += 8)
        out[(size_t)(bx + ty + j) * R + by + tx] = __float2half_rn(t[tx][ty + j]);
}

// ---------------------------------------------------------------------------
// fp16 GEMM (byte-identical to R11 — protected win):
// BM=BN=128, BK=64, 256 thr, 3-stage cp.async, ldmatrix fragments.
// ---------------------------------------------------------------------------
#define GBM 128
#define GBN 128
#define GBK 64
#define AROW 36
#define G_TILE (128 * AROW)
#define STAGES 3
#define GEMM_SMEM (2 * STAGES * G_TILE * 4)   // 110592 B

__global__ __launch_bounds__(256, 2)
void h_gemm_kernel(const __half* __restrict__ A, const __half* __restrict__ Bt,
                   const float* __restrict__ bias,
                   float* __restrict__ Cf, __half* __restrict__ Ch,
                   float* __restrict__ cache,
                   int M, int N, int K) {
    extern __shared__ uint32_t smu[];
    const uint32_t sbase = smem_u32(smu);
    const uint32_t sA = sbase;
    const uint32_t sB = sbase + STAGES * G_TILE * 4;

    const int tid  = threadIdx.x;
    const int wid  = tid >> 5;
    const int lane = tid & 31;
    const int g    = lane >> 2;
    const int tg   = lane & 3;
    const int wm   = (wid & 3) * 32;
    const int wn   = (wid >> 2) * 64;
    const int m0   = blockIdx.y * GBM;
    const int n0   = blockIdx.x * GBN;
    const int rowu4 = K / 8;

    const uint4* gA[4]; const uint4* gB[4]; uint32_t so[4];
#pragma unroll
    for (int i = 0; i < 4; i++) {
        int idx = i * 256 + tid;
        int r = idx >> 3, c4 = idx & 7;
        gA[i] = (const uint4*)A + (size_t)(m0 + r) * rowu4 + c4;
        gB[i] = (const uint4*)Bt + (size_t)(n0 + r) * rowu4 + c4;
        so[i] = (uint32_t)(r * AROW + c4 * 4) * 4;
    }

    const int mrow = lane & 7;
    const int msel = lane >> 3;
    uint32_t aOff[2];
#pragma unroll
    for (int i = 0; i < 2; i++)
        aOff[i] = (uint32_t)(((wm + 16 * i + (msel & 1) * 8 + mrow) * AROW
                             + (msel >> 1) * 4) * 4);
    uint32_t bOff[4];
#pragma unroll
    for (int jj = 0; jj < 4; jj++)
        bOff[jj] = (uint32_t)(((wn + 16 * jj + (msel >> 1) * 8 + mrow) * AROW
                              + (msel & 1) * 4) * 4);

    float c[2][8][4];
#pragma unroll
    for (int i = 0; i < 2; i++)
#pragma unroll
        for (int j = 0; j < 8; j++)
#pragma unroll
            for (int q = 0; q < 4; q++) c[i][j][q] = 0.0f;

    const int NC = K / GBK;

#pragma unroll
    for (int st = 0; st < 2; st++) {
        uint32_t aS = sA + st * G_TILE * 4;
        uint32_t bS = sB + st * G_TILE * 4;
#pragma unroll
        for (int i = 0; i < 4; i++) {
            cp16(aS + so[i], gA[i] + st * 8);
            cp16(bS + so[i], gB[i] + st * 8);
        }
        CP_COMMIT();
    }

    for (int ch = 0; ch < NC; ++ch) {
        if (ch + 1 < NC) { CP_WAIT1(); } else { CP_WAIT0(); }
        __syncthreads();

        if (ch + 2 < NC) {
            int st = (ch + 2) % STAGES;
            uint32_t aS = sA + st * G_TILE * 4;
            uint32_t bS = sB + st * G_TILE * 4;
#pragma unroll
            for (int i = 0; i < 4; i++) {
                cp16(aS + so[i], gA[i] + (ch + 2) * 8);
                cp16(bS + so[i], gB[i] + (ch + 2) * 8);
            }
            CP_COMMIT();
        }

        const int cur = ch % STAGES;
        const uint32_t aS = sA + cur * G_TILE * 4;
        const uint32_t bS = sB + cur * G_TILE * 4;

#pragma unroll
        for (int s = 0; s < 4; s++) {
            uint32_t a[2][4], bq[4][4];
#pragma unroll
            for (int i = 0; i < 2; i++)
                ldsm_x4(a[i], aS + aOff[i] + s * 32);
#pragma unroll
            for (int jj = 0; jj < 4; jj++)
                ldsm_x4(bq[jj], bS + bOff[jj] + s * 32);
#pragma unroll
            for (int i = 0; i < 2; i++)
#pragma unroll
                for (int jj = 0; jj < 4; jj++) {
                    mma_h(c[i][2 * jj],     a[i], &bq[jj][0]);
                    mma_h(c[i][2 * jj + 1], a[i], &bq[jj][2]);
                }
        }
    }

#pragma unroll
    for (int i = 0; i < 2; i++) {
        int row = m0 + wm + 16 * i + g;
#pragma unroll
        for (int j = 0; j < 8; j++) {
            int col = n0 + wn + 8 * j + 2 * tg;
            float2 bv = *(const float2*)(bias + col);
            float2 o0, o1;
            o0.x = c[i][j][0] + bv.x;  o0.y = c[i][j][1] + bv.y;
            o1.x = c[i][j][2] + bv.x;  o1.y = c[i][j][3] + bv.y;
            if (Cf != nullptr) {
                *(float2*)(Cf + (size_t)row * N + col) = o0;
                *(float2*)(Cf + (size_t)(row + 8) * N + col) = o1;
            }
            if (Ch != nullptr) {
                *(uint32_t*)(Ch + (size_t)row * N + col) = pack_h2(o0.x, o0.y);
                *(uint32_t*)(Ch + (size_t)(row + 8) * N + col) = pack_h2(o1.x, o1.y);
            }
            if (cache != nullptr && col >= CC) {
                int cc = col - CC;
                *(float2*)(cache + (size_t)row * (2 * CC) + cc) = o0;
                *(float2*)(cache + (size_t)(row + 8) * (2 * CC) + cc) = o1;
            }
        }
    }
}

// ---------------------------------------------------------------------------
// Flash attention, fp16 mma (causal).
// NEW: P kept in registers (C-frag -> A-frag identity), K/V double-buffered
// via cp.async (load kt+1 overlaps compute kt). 2 CTAs/SM preserved.
// smem (u32): Qs[128][68], then 2 x (K[64][68], V[64][68])  = 104448 B
// ---------------------------------------------------------------------------
#define AQW 68
#define KV_TILE (64 * AQW)               // 4352 u32 per operand per buffer
#define ATTN_SMEM_U32 (128 * AQW + 4 * KV_TILE)
#define ATTN_SMEM_BYTES (ATTN_SMEM_U32 * 4)

__global__ __launch_bounds__(256, 2)
void attn_h_kernel(const __half* __restrict__ qkv, __half* __restrict__ y) {
    extern __shared__ uint32_t smu[];
    uint32_t* Qs = smu;                   // [128][68]

    const uint32_t sbase = smem_u32(smu);
    const uint32_t sQ  = sbase;
    const uint32_t sKV = sbase + 128 * AQW * 4;   // buf b: K at b*2*KV_TILE, V at +KV_TILE

    const int tid  = threadIdx.x;
    const int wid  = tid >> 5;
    const int lane = tid & 31;
    const int g    = lane >> 2;
    const int tg   = lane & 3;
    const int bh   = blockIdx.x;
    const int b    = bh >> 4;
    const int h    = bh & 15;
    const int qt   = gridDim.y - 1 - blockIdx.y;
    const int q0   = qt * 128;
    const int wr0  = wid * 16;

    const float SCALE = 0.08838834764831845f;
    const int ROWU4 = QKV_N / 8;          // 768

    const uint4* qkv4 = (const uint4*)qkv;
    const size_t bbase = (size_t)b * TT * ROWU4;
    const int qoff = h * 16;
    const int koff = 256 + h * 16;
    const int voff = 512 + h * 16;

    // per-thread cp.async coords for K/V tiles (64 rows x 16 uint4 each)
    int kvr[4], kvc[4]; uint32_t kvso[4];
#pragma unroll
    for (int p = 0; p < 4; p++) {
        int i = tid + 256 * p;
        kvr[p] = i >> 4; kvc[p] = i & 15;
        kvso[p] = (uint32_t)(kvr[p] * AQW + kvc[p] * 4) * 4;
    }

    // ldmatrix lane offsets
    const int mrow = lane & 7;
    const int msel = lane >> 3;
    const uint32_t qOff = (uint32_t)(((wr0 + (msel & 1) * 8 + mrow) * AQW
                                     + (msel >> 1) * 4) * 4);
    uint32_t kOff[4];
#pragma unroll
    for (int jj = 0; jj < 4; jj++)
        kOff[jj] = (uint32_t)(((16 * jj + (msel >> 1) * 8 + mrow) * AQW
                              + (msel & 1) * 4) * 4);
    uint32_t vOff[8];
#pragma unroll
    for (int v = 0; v < 8; v++)
        vOff[v] = (uint32_t)((((msel & 1) * 8 + mrow) * AQW
                             + (2 * v + (msel >> 1)) * 4) * 4);

    // Load Q tile (128 rows x 16 uint4)
#pragma unroll
    for (int p = 0; p < 8; p++) {
        int i = tid + 256 * p;
        int r = i >> 4, c4 = i & 15;
        uint4 v = qkv4[bbase + (size_t)(q0 + r) * ROWU4 + qoff + c4];
        *(uint4*)&Qs[r * AQW + c4 * 4] = v;
    }

    float m_prev[2] = {-1e30f, -1e30f};
    float l_acc[2]  = {0.0f, 0.0f};
    float acc[16][4];
#pragma unroll
    for (int nj = 0; nj < 16; nj++)
#pragma unroll
        for (int q = 0; q < 4; q++) acc[nj][q] = 0.0f;

    const int ntiles = 2 * qt + 2;

    // Prologue: issue tile 0 into buffer 0
    {
        uint32_t kS = sKV;
        uint32_t vS = sKV + KV_TILE * 4;
#pragma unroll
        for (int p = 0; p < 4; p++) {
            const uint4* src = qkv4 + bbase + (size_t)kvr[p] * ROWU4;
            cp16(kS + kvso[p], src + koff + kvc[p]);
            cp16(vS + kvso[p], src + voff + kvc[p]);
        }
        CP_COMMIT();
    }

    for (int kt = 0; kt < ntiles; ++kt) {
        CP_WAIT0();
        __syncthreads();   // tile kt visible to all; prior reads of next buf done

        if (kt + 1 < ntiles) {
            const int nk0 = (kt + 1) * 64;
            uint32_t kS = sKV + (uint32_t)(((kt + 1) & 1) * 2 * KV_TILE) * 4;
            uint32_t vS = kS + KV_TILE * 4;
#pragma unroll
            for (int p = 0; p < 4; p++) {
                const uint4* src = qkv4 + bbase + (size_t)(nk0 + kvr[p]) * ROWU4;
                cp16(kS + kvso[p], src + koff + kvc[p]);
                cp16(vS + kvso[p], src + voff + kvc[p]);
            }
            CP_COMMIT();
        }

        const int k0 = kt * 64;
        const uint32_t sK = sKV + (uint32_t)((kt & 1) * 2 * KV_TILE) * 4;
        const uint32_t sV = sK + KV_TILE * 4;

        // ---- S = Q K^T : 16 x 64 per warp, ldmatrix fragments ----
        float cs[8][4];
#pragma unroll
        for (int j = 0; j < 8; j++)
#pragma unroll
            for (int q = 0; q < 4; q++) cs[j][q] = 0.0f;

#pragma unroll
        for (int s = 0; s < 8; s++) {
            uint32_t a[4], bq[4][4];
            ldsm_x4(a, sQ + qOff + s * 32);
#pragma unroll
            for (int jj = 0; jj < 4; jj++)
                ldsm_x4(bq[jj], sK + kOff[jj] + s * 32);
#pragma unroll
            for (int jj = 0; jj < 4; jj++) {
                mma_h(cs[2 * jj],     a, &bq[jj][0]);
                mma_h(cs[2 * jj + 1], a, &bq[jj][2]);
            }
        }

        // ---- scale + causal mask + row max ----
        const int gr0 = q0 + wr0 + g;
        const int gr1 = gr0 + 8;
        float mx0 = -1e30f, mx1 = -1e30f;
#pragma unroll
        for (int j = 0; j < 8; j++) {
            int gc0 = k0 + 8 * j + 2 * tg;
            int gc1 = gc0 + 1;
            float s0 = cs[j][0] * SCALE; if (gc0 > gr0) s0 = -1e30f;
            float s1 = cs[j][1] * SCALE; if (gc1 > gr0) s1 = -1e30f;
            float s2 = cs[j][2] * SCALE; if (gc0 > gr1) s2 = -1e30f;
            float s3 = cs[j][3] * SCALE; if (gc1 > gr1) s3 = -1e30f;
            cs[j][0] = s0; cs[j][1] = s1; cs[j][2] = s2; cs[j][3] = s3;
            mx0 = fmaxf(mx0, fmaxf(s0, s1));
            mx1 = fmaxf(mx1, fmaxf(s2, s3));
        }
        mx0 = fmaxf(mx0, __shfl_xor_sync(0xffffffffu, mx0, 1));
        mx0 = fmaxf(mx0, __shfl_xor_sync(0xffffffffu, mx0, 2));
        mx1 = fmaxf(mx1, __shfl_xor_sync(0xffffffffu, mx1, 1));
        mx1 = fmaxf(mx1, __shfl_xor_sync(0xffffffffu, mx1, 2));

        float mn0 = fmaxf(m_prev[0], mx0);
        float mn1 = fmaxf(m_prev[1], mx1);
        float f0 = __expf(m_prev[0] - mn0);
        float f1 = __expf(m_prev[1] - mn1);
        m_prev[0] = mn0; m_prev[1] = mn1;

        // ---- exp + pack P directly into A-fragments (no smem round-trip) ----
        uint32_t a_pv[4][4];
        float ls0 = 0.0f, ls1 = 0.0f;
#pragma unroll
        for (int s = 0; s < 4; s++) {
#pragma unroll
            for (int half = 0; half < 2; half++) {
                int j = 2 * s + half;
                float p0 = __expf(cs[j][0] - mn0);
                float p1 = __expf(cs[j][1] - mn0);
                float p2 = __expf(cs[j][2] - mn1);
                float p3 = __expf(cs[j][3] - mn1);
                ls0 += p0 + p1;
                ls1 += p2 + p3;
                a_pv[s][2 * half]     = pack_h2(p0, p1);   // row g
                a_pv[s][2 * half + 1] = pack_h2(p2, p3);   // row g+8
            }
        }
        ls0 += __shfl_xor_sync(0xffffffffu, ls0, 1);
        ls0 += __shfl_xor_sync(0xffffffffu, ls0, 2);
        ls1 += __shfl_xor_sync(0xffffffffu, ls1, 1);
        ls1 += __shfl_xor_sync(0xffffffffu, ls1, 2);
        l_acc[0] = l_acc[0] * f0 + ls0;
        l_acc[1] = l_acc[1] * f1 + ls1;

#pragma unroll
        for (int nj = 0; nj < 16; nj++) {
            acc[nj][0] *= f0; acc[nj][1] *= f0;
            acc[nj][2] *= f1; acc[nj][3] *= f1;
        }

        // ---- acc += P @ V : reg A-fragments + trans-ldmatrix V ----
#pragma unroll
        for (int s = 0; s < 4; s++) {
            const uint32_t vsbase = sV + (uint32_t)(s * 16 * AQW * 4);
#pragma unroll
            for (int v = 0; v < 8; v++) {
                uint32_t bq[4];
                ldsm_x4_t(bq, vsbase + vOff[v]);
                mma_h(acc[2 * v],     a_pv[s], &bq[0]);
                mma_h(acc[2 * v + 1], a_pv[s], &bq[2]);
            }
        }
    }

    float inv0 = 1.0f / l_acc[0];
    float inv1 = 1.0f / l_acc[1];
    size_t row0 = (size_t)(b * TT + q0 + wr0 + g);
    size_t row1 = row0 + 8;
#pragma unroll
    for (int nj = 0; nj < 16; nj++) {
        int col = h * DH + 8 * nj + 2 * tg;
        *(uint32_t*)(y + row0 * CC + col) = pack_h2(acc[nj][0] * inv0, acc[nj][1] * inv0);
        *(uint32_t*)(y + row1 * CC + col) = pack_h2(acc[nj][2] * inv1, acc[nj][3] * inv1);
    }
}

// ---------------------------------------------------------------------------
extern "C" void kernel_launch(void* const* d_in, const int* in_sizes, int n_in,
                              void* d_out, int out_size) {
    (void)in_sizes; (void)n_in; (void)out_size;
    const float* x      = (const float*)d_in[0];
    const float* W_attn = (const float*)d_in[2];
    const float* b_attn = (const float*)d_in[3];
    const float* W_proj = (const float*)d_in[4];
    const float* b_proj = (const float*)d_in[5];

    float* out   = (float*)d_out;
    float* y_out = out;
    float* cache = out + (size_t)M_ROWS * CC;

    __half *xh, *qkvh, *yh, *wath, *wpth;
    cudaGetSymbolAddress((void**)&xh,   g_xh);
    cudaGetSymbolAddress((void**)&qkvh, g_qkvh);
    cudaGetSymbolAddress((void**)&yh,   g_yh);
    cudaGetSymbolAddress((void**)&wath, g_wath);
    cudaGetSymbolAddress((void**)&wpth, g_wpth);

    cudaFuncSetAttribute(h_gemm_kernel,
                         cudaFuncAttributeMaxDynamicSharedMemorySize, GEMM_SMEM);
    cudaFuncSetAttribute(attn_h_kernel,
                         cudaFuncAttributeMaxDynamicSharedMemorySize, ATTN_SMEM_BYTES);

    // 0) pre-pass conversions
    f2h_kernel<<<(int)((size_t)M_ROWS * CC / 4 / 256), 256>>>(x, xh);
    {
        dim3 blk(32, 8);
        trans_h_kernel<<<dim3(QKV_N / 32, CC / 32), blk>>>(W_attn, wath, CC, QKV_N);
        trans_h_kernel<<<dim3(CC / 32, CC / 32), blk>>>(W_proj, wpth, CC, CC);
    }
    // 1) qkv = x @ W_attn + b_attn -> qkv fp16 + fused f32 cache
    {
        dim3 grid(QKV_N / GBN, M_ROWS / GBM);   // (48, 32)
        h_gemm_kernel<<<grid, 256, GEMM_SMEM>>>(xh, wath, b_attn,
                                                nullptr, qkvh, cache,
                                                M_ROWS, QKV_N, CC);
    }
    // 2) flash attention fp16 -> yh
    {
        dim3 grid(BB * HH, TT / 128);           // (32, 16)
        attn_h_kernel<<<grid, 256, ATTN_SMEM_BYTES>>>(qkvh, yh);
    }
    // 3) y = yh @ W_proj + b_proj -> f32 out
    {
        dim3 grid(CC / GBN, M_ROWS / GBM);      // (16, 32)
        h_gemm_kernel<<<grid, 256, GEMM_SMEM>>>(yh, wpth, b_proj,
                                                y_out, nullptr, nullptr,
                                                M_ROWS, CC, CC);
    }
}